// round 12
// baseline (speedup 1.0000x reference)
#include <cuda_runtime.h>
#include <cuda_bf16.h>
#include <cuda_fp16.h>
#include <math.h>

#define H      2048
#define NH     32
#define NKV    8
#define HD     64
#define GROUPS 4
#define FF     5632
#define BATCH  2
#define SEQ    2048
#define M_TOK  (BATCH*SEQ)
#define QKV_N  3072

#define ATTN_SMEM   83456
#define GEMM_SMEM   65536
#define GEMM16_SMEM 49152

// bf16 weight planes (QKV + O only)
#define OFF_Q  ((size_t)0)
#define OFF_K  (OFF_Q + (size_t)2048*2048)
#define OFF_V  (OFF_K + (size_t)512*2048)
#define OFF_O  (OFF_V + (size_t)512*2048)
#define W_TOTAL (OFF_O + (size_t)2048*2048)
// fp16 weight planes (MLP)
#define OFF16_G ((size_t)0)
#define OFF16_U (OFF16_G + (size_t)5632*2048)
#define OFF16_D (OFF16_U + (size_t)5632*2048)
#define W16_TOTAL (OFF16_D + (size_t)2048*5632)

// ---------------- scratch (device globals: allocation-guard safe) ----------------
__device__ float g_qkv[M_TOK*QKV_N];
__device__ float g_hidden[M_TOK*H];
__device__ float g_gate[M_TOK*FF];
__device__ __nv_bfloat16 g_xn_h[M_TOK*H];
__device__ __nv_bfloat16 g_xn_l[M_TOK*H];
__device__ __nv_bfloat16 g_ao_h[M_TOK*H];
__device__ __nv_bfloat16 g_ao_l[M_TOK*H];
__device__ __nv_bfloat16 g_w_h[W_TOTAL];
__device__ __nv_bfloat16 g_w_l[W_TOTAL];
__device__ __half g_w16_h[W16_TOTAL];
__device__ __half g_w16_l[W16_TOTAL];
__device__ __half g_xn16[M_TOK*H];
__device__ __half g_act16[M_TOK*FF];
// rope'd attention input planes (Q pre-scaled by 1/8)
__device__ __nv_bfloat16 g_qp_h[M_TOK*H];
__device__ __nv_bfloat16 g_qp_l[M_TOK*H];
__device__ __nv_bfloat16 g_kp_h[M_TOK*NKV*HD];
__device__ __nv_bfloat16 g_kp_l[M_TOK*NKV*HD];
__device__ __nv_bfloat16 g_vp_h[M_TOK*NKV*HD];
__device__ __nv_bfloat16 g_vp_l[M_TOK*NKV*HD];

// ---------------- helpers ----------------
__device__ __forceinline__ unsigned pack_bf2(float a, float b) {
    __nv_bfloat162 t = __floats2bfloat162_rn(a, b);
    return *(unsigned*)&t;
}
__device__ __forceinline__ unsigned pack_h2(float a, float b) {
    __half2 t = __floats2half2_rn(a, b);
    return *(unsigned*)&t;
}
__device__ __forceinline__ void split1(float x, float& hi, float& lo) {
    __nv_bfloat16 hb = __float2bfloat16(x);
    hi = __bfloat162float(hb);
    lo = x - hi;
}
__device__ __forceinline__ void split1h(float x, float& hi, float& lo) {
    __half hb = __float2half_rn(x);
    hi = __half2float(hb);
    lo = x - hi;
}

#define SW64(x)   ((unsigned)(x) ^ ((((unsigned)(x)) >> 3) & 0x30u))
#define SW128X(x) ((unsigned)(x) ^ ((((unsigned)(x)) >> 3) & 0x70u))

#define CPA16(dst, src) \
    asm volatile("cp.async.cg.shared.global [%0], [%1], 16;" :: "r"(dst), "l"(src))
#define CPCOMMIT() asm volatile("cp.async.commit_group;")
#define CPWAIT0()  asm volatile("cp.async.wait_group 0;")

#define LDSM4(r, a) \
    asm volatile("ldmatrix.sync.aligned.m8n8.x4.shared.b16 {%0,%1,%2,%3}, [%4];" \
                 : "=r"((r)[0]), "=r"((r)[1]), "=r"((r)[2]), "=r"((r)[3]) : "r"(a))
#define LDSM4T(r, a) \
    asm volatile("ldmatrix.sync.aligned.m8n8.x4.trans.shared.b16 {%0,%1,%2,%3}, [%4];" \
                 : "=r"((r)[0]), "=r"((r)[1]), "=r"((r)[2]), "=r"((r)[3]) : "r"(a))

#define MMA_B16(c, a, b0v, b1v) \
    asm volatile("mma.sync.aligned.m16n8k16.row.col.f32.bf16.bf16.f32 " \
                 "{%0,%1,%2,%3},{%4,%5,%6,%7},{%8,%9},{%0,%1,%2,%3};" \
                 : "+f"((c)[0]), "+f"((c)[1]), "+f"((c)[2]), "+f"((c)[3]) \
                 : "r"((a)[0]), "r"((a)[1]), "r"((a)[2]), "r"((a)[3]), "r"(b0v), "r"(b1v))
#define MMA_F16(c, a, b0v, b1v) \
    asm volatile("mma.sync.aligned.m16n8k16.row.col.f32.f16.f16.f32 " \
                 "{%0,%1,%2,%3},{%4,%5,%6,%7},{%8,%9},{%0,%1,%2,%3};" \
                 : "+f"((c)[0]), "+f"((c)[1]), "+f"((c)[2]), "+f"((c)[3]) \
                 : "r"((a)[0]), "r"((a)[1]), "r"((a)[2]), "r"((a)[3]), "r"(b0v), "r"(b1v))

// ---------------- weight binarize + bf16 hi/lo split prepass ----------------
__global__ void binsplit_kernel(const float* __restrict__ src,
                                __nv_bfloat16* __restrict__ dh,
                                __nv_bfloat16* __restrict__ dl,
                                const float* __restrict__ kkp, const float* __restrict__ aap) {
    const float kk = kkp[0], aa = aap[0];
    size_t i = ((size_t)blockIdx.x * 256 + threadIdx.x) * 4;
    float4 w = *(const float4*)(src + i);
    float v[4] = {w.x, w.y, w.z, w.w};
    float hv[4], lv[4];
    #pragma unroll
    for (int j = 0; j < 4; j++) {
        float b = aa * fminf(fmaxf(kk * v[j], -1.0f), 1.0f);
        split1(b, hv[j], lv[j]);
    }
    *(uint2*)(dh + i) = make_uint2(pack_bf2(hv[0], hv[1]), pack_bf2(hv[2], hv[3]));
    *(uint2*)(dl + i) = make_uint2(pack_bf2(lv[0], lv[1]), pack_bf2(lv[2], lv[3]));
}

// ---------------- weight binarize + fp16 hi/lo split prepass (with output scale) ----------------
__global__ void binsplit16_kernel(const float* __restrict__ src,
                                  __half* __restrict__ dh,
                                  __half* __restrict__ dl,
                                  const float* __restrict__ kkp, const float* __restrict__ aap,
                                  float scale) {
    const float kk = kkp[0], aa = aap[0];
    size_t i = ((size_t)blockIdx.x * 256 + threadIdx.x) * 4;
    float4 w = *(const float4*)(src + i);
    float v[4] = {w.x, w.y, w.z, w.w};
    float hv[4], lv[4];
    #pragma unroll
    for (int j = 0; j < 4; j++) {
        float b = aa * fminf(fmaxf(kk * v[j], -1.0f), 1.0f) * scale;
        split1h(b, hv[j], lv[j]);
    }
    *(uint2*)(dh + i) = make_uint2(pack_h2(hv[0], hv[1]), pack_h2(hv[2], hv[3]));
    *(uint2*)(dl + i) = make_uint2(pack_h2(lv[0], lv[1]), pack_h2(lv[2], lv[3]));
}

// ---------------- RMSNorm -> bf16 hi/lo planes ----------------
__global__ void rmsnorm_kernel(const float* __restrict__ x, const float* __restrict__ w,
                               __nv_bfloat16* __restrict__ yh, __nv_bfloat16* __restrict__ yl) {
    int row = blockIdx.x;
    const float4* xr = (const float4*)(x + (size_t)row * H);
    const float4* wv = (const float4*)w;
    int tid = threadIdx.x;
    float4 a = xr[tid];
    float4 b = xr[tid + 256];
    float ss = a.x*a.x + a.y*a.y + a.z*a.z + a.w*a.w
             + b.x*b.x + b.y*b.y + b.z*b.z + b.w*b.w;
    #pragma unroll
    for (int o = 16; o; o >>= 1) ss += __shfl_xor_sync(0xffffffffu, ss, o);
    __shared__ float ws[8];
    if ((tid & 31) == 0) ws[tid >> 5] = ss;
    __syncthreads();
    float tot = ws[0]+ws[1]+ws[2]+ws[3]+ws[4]+ws[5]+ws[6]+ws[7];
    float r = rsqrtf(tot * (1.0f / (float)H) + 1e-5f);
    float4 w0 = wv[tid], w1 = wv[tid + 256];
    float o0[4] = {a.x*r*w0.x, a.y*r*w0.y, a.z*r*w0.z, a.w*r*w0.w};
    float o1[4] = {b.x*r*w1.x, b.y*r*w1.y, b.z*r*w1.z, b.w*r*w1.w};
    float h0[4], l0[4], h1[4], l1[4];
    #pragma unroll
    for (int j = 0; j < 4; j++) { split1(o0[j], h0[j], l0[j]); split1(o1[j], h1[j], l1[j]); }
    size_t base = (size_t)row * H + 4 * tid;
    *(uint2*)(yh + base)        = make_uint2(pack_bf2(h0[0],h0[1]), pack_bf2(h0[2],h0[3]));
    *(uint2*)(yl + base)        = make_uint2(pack_bf2(l0[0],l0[1]), pack_bf2(l0[2],l0[3]));
    *(uint2*)(yh + base + 1024) = make_uint2(pack_bf2(h1[0],h1[1]), pack_bf2(h1[2],h1[3]));
    *(uint2*)(yl + base + 1024) = make_uint2(pack_bf2(l1[0],l1[1]), pack_bf2(l1[2],l1[3]));
}

// ---------------- RMSNorm -> fp16 single plane ----------------
__global__ void rmsnorm16_kernel(const float* __restrict__ x, const float* __restrict__ w,
                                 __half* __restrict__ y) {
    int row = blockIdx.x;
    const float4* xr = (const float4*)(x + (size_t)row * H);
    const float4* wv = (const float4*)w;
    int tid = threadIdx.x;
    float4 a = xr[tid];
    float4 b = xr[tid + 256];
    float ss = a.x*a.x + a.y*a.y + a.z*a.z + a.w*a.w
             + b.x*b.x + b.y*b.y + b.z*b.z + b.w*b.w;
    #pragma unroll
    for (int o = 16; o; o >>= 1) ss += __shfl_xor_sync(0xffffffffu, ss, o);
    __shared__ float ws[8];
    if ((tid & 31) == 0) ws[tid >> 5] = ss;
    __syncthreads();
    float tot = ws[0]+ws[1]+ws[2]+ws[3]+ws[4]+ws[5]+ws[6]+ws[7];
    float r = rsqrtf(tot * (1.0f / (float)H) + 1e-5f);
    float4 w0 = wv[tid], w1 = wv[tid + 256];
    size_t base = (size_t)row * H + 4 * tid;
    *(uint2*)(y + base)        = make_uint2(pack_h2(a.x*r*w0.x, a.y*r*w0.y), pack_h2(a.z*r*w0.z, a.w*r*w0.w));
    *(uint2*)(y + base + 1024) = make_uint2(pack_h2(b.x*r*w1.x, b.y*r*w1.y), pack_h2(b.z*r*w1.z, b.w*r*w1.w));
}

// ---------------- tensor-core GEMM: 2-stage cp.async, bf16 hi/lo split, 2 CTA/SM ----------------
// MODE 0: C fp32. MODE 1: C = acc + X.
template<int MODE>
__global__ void __launch_bounds__(256, 2) gemm_mma(
    const __nv_bfloat16* __restrict__ Ah, const __nv_bfloat16* __restrict__ Al,
    const __nv_bfloat16* __restrict__ Wh, const __nv_bfloat16* __restrict__ Wl,
    const float* X, float* __restrict__ C,
    int N, int K)
{
    extern __shared__ unsigned char smem[];
    unsigned sbase = (unsigned)__cvta_generic_to_shared(smem);

    int tid = threadIdx.x;
    int bm = blockIdx.y << 7, bn = blockIdx.x << 7;

    int r0 = tid >> 2, c0 = tid & 3;
    const __nv_bfloat16* pA = Ah + (size_t)(bm + r0) * K + c0 * 8;
    const __nv_bfloat16* pW = Wh + (size_t)(bn + r0) * K + c0 * 8;
    ptrdiff_t dAl = Al - Ah;
    ptrdiff_t dWl = Wl - Wh;
    ptrdiff_t d64 = (ptrdiff_t)64 * K;
    unsigned dOff = SW64(64 * r0 + 16 * c0);

    int warp = tid >> 5, lane = tid & 31;
    int m0 = (warp & 1) << 6;
    int n0 = (warp >> 1) << 5;
    int lr = lane & 15;
    int lc = lane >> 4;
    unsigned aOff[4], bOff[2];
    #pragma unroll
    for (int i = 0; i < 4; i++) aOff[i] = 64u * (m0 + 16 * i + lr) + 16u * lc;
    #pragma unroll
    for (int j = 0; j < 2; j++) bOff[j] = 64u * (n0 + 16 * j + lr) + 16u * lc;

    int fr = lane >> 2, kp = lane & 3;

    float acc[4][4][4];
    #pragma unroll
    for (int i = 0; i < 4; i++)
        #pragma unroll
        for (int j = 0; j < 4; j++)
            #pragma unroll
            for (int r = 0; r < 4; r++) acc[i][j][r] = 0.0f;

    int nk = K >> 5;

    {
        unsigned b0 = sbase;
        CPA16(b0 + dOff,                 pA);
        CPA16(b0 + dOff + 4096,          pA + d64);
        CPA16(b0 + 8192  + dOff,         pA + dAl);
        CPA16(b0 + 8192  + dOff + 4096,  pA + dAl + d64);
        CPA16(b0 + 16384 + dOff,         pW);
        CPA16(b0 + 16384 + dOff + 4096,  pW + d64);
        CPA16(b0 + 24576 + dOff,         pW + dWl);
        CPA16(b0 + 24576 + dOff + 4096,  pW + dWl + d64);
        CPCOMMIT();
    }

    for (int kb = 0; kb < nk; kb++) {
        CPWAIT0();
        __syncthreads();
        if (kb + 1 < nk) {
            int ko = (kb + 1) << 5;
            unsigned b0 = sbase + (((kb + 1) & 1) << 15);
            CPA16(b0 + dOff,                 pA + ko);
            CPA16(b0 + dOff + 4096,          pA + d64 + ko);
            CPA16(b0 + 8192  + dOff,         pA + dAl + ko);
            CPA16(b0 + 8192  + dOff + 4096,  pA + dAl + d64 + ko);
            CPA16(b0 + 16384 + dOff,         pW + ko);
            CPA16(b0 + 16384 + dOff + 4096,  pW + d64 + ko);
            CPA16(b0 + 24576 + dOff,         pW + dWl + ko);
            CPA16(b0 + 24576 + dOff + 4096,  pW + dWl + d64 + ko);
            CPCOMMIT();
        }

        unsigned bAh = sbase + ((kb & 1) << 15);
        unsigned bAl = bAh + 8192, bWh = bAh + 16384, bWl = bAh + 24576;

        #pragma unroll
        for (int s = 0; s < 2; s++) {
            unsigned so = s << 5;
            unsigned aH[4][4], aL[4][4], bH[2][4], bL[2][4];
            #pragma unroll
            for (int i = 0; i < 4; i++) LDSM4(aH[i], bAh + SW64(aOff[i] + so));
            #pragma unroll
            for (int j = 0; j < 2; j++) LDSM4(bH[j], bWh + SW64(bOff[j] + so));
            #pragma unroll
            for (int i = 0; i < 4; i++)
                #pragma unroll
                for (int j = 0; j < 2; j++) {
                    MMA_B16(acc[i][2*j],   aH[i], bH[j][0], bH[j][2]);
                    MMA_B16(acc[i][2*j+1], aH[i], bH[j][1], bH[j][3]);
                }
            #pragma unroll
            for (int j = 0; j < 2; j++) LDSM4(bL[j], bWl + SW64(bOff[j] + so));
            #pragma unroll
            for (int i = 0; i < 4; i++)
                #pragma unroll
                for (int j = 0; j < 2; j++) {
                    MMA_B16(acc[i][2*j],   aH[i], bL[j][0], bL[j][2]);
                    MMA_B16(acc[i][2*j+1], aH[i], bL[j][1], bL[j][3]);
                }
            #pragma unroll
            for (int i = 0; i < 4; i++) LDSM4(aL[i], bAl + SW64(aOff[i] + so));
            #pragma unroll
            for (int i = 0; i < 4; i++)
                #pragma unroll
                for (int j = 0; j < 2; j++) {
                    MMA_B16(acc[i][2*j],   aL[i], bH[j][0], bH[j][2]);
                    MMA_B16(acc[i][2*j+1], aL[i], bH[j][1], bH[j][3]);
                }
        }
        __syncthreads();
    }

    #pragma unroll
    for (int i = 0; i < 4; i++) {
        #pragma unroll
        for (int j = 0; j < 4; j++) {
            int row0 = bm + m0 + 16 * i + fr;
            int col  = bn + n0 + 8 * j + kp * 2;
            #pragma unroll
            for (int half = 0; half < 2; half++) {
                int row = row0 + half * 8;
                float v0 = acc[i][j][2 * half + 0];
                float v1 = acc[i][j][2 * half + 1];
                size_t off = (size_t)row * N + col;
                if (MODE == 0) {
                    *(float2*)(C + off) = make_float2(v0, v1);
                } else {
                    float2 xr = *(const float2*)(X + off);
                    *(float2*)(C + off) = make_float2(v0 + xr.x, v1 + xr.y);
                }
            }
        }
    }
}

// ---------------- tensor-core GEMM: fp16 2-pass (A single plane, W hi/lo), 2 CTA/SM ----------------
// MODE 0: C fp32. MODE 1: C = acc + X (fp32). MODE 2: C16 = silu(X)*acc*(1/16) fp16.
template<int MODE>
__global__ void __launch_bounds__(256, 2) gemm_f16(
    const __half* __restrict__ A,
    const __half* __restrict__ Wh_, const __half* __restrict__ Wl_,
    const float* X, float* C, __half* C16,
    int N, int K)
{
    extern __shared__ unsigned char smem[];
    unsigned sbase = (unsigned)__cvta_generic_to_shared(smem);

    int tid = threadIdx.x;
    int bm = blockIdx.y << 7, bn = blockIdx.x << 7;

    int r0 = tid >> 2, c0 = tid & 3;
    const __half* pA = A + (size_t)(bm + r0) * K + c0 * 8;
    const __half* pW = Wh_ + (size_t)(bn + r0) * K + c0 * 8;
    ptrdiff_t dWl = Wl_ - Wh_;
    ptrdiff_t d64 = (ptrdiff_t)64 * K;
    unsigned dOff = SW64(64 * r0 + 16 * c0);

    int warp = tid >> 5, lane = tid & 31;
    int m0 = (warp & 1) << 6;
    int n0 = (warp >> 1) << 5;
    int lr = lane & 15;
    int lc = lane >> 4;
    unsigned aOff[4], bOff[2];
    #pragma unroll
    for (int i = 0; i < 4; i++) aOff[i] = 64u * (m0 + 16 * i + lr) + 16u * lc;
    #pragma unroll
    for (int j = 0; j < 2; j++) bOff[j] = 64u * (n0 + 16 * j + lr) + 16u * lc;

    int fr = lane >> 2, kp = lane & 3;

    float acc[4][4][4];
    #pragma unroll
    for (int i = 0; i < 4; i++)
        #pragma unroll
        for (int j = 0; j < 4; j++)
            #pragma unroll
            for (int r = 0; r < 4; r++) acc[i][j][r] = 0.0f;

    int nk = K >> 5;

    {
        unsigned b0 = sbase;
        CPA16(b0 + dOff,                 pA);
        CPA16(b0 + dOff + 4096,          pA + d64);
        CPA16(b0 + 8192  + dOff,         pW);
        CPA16(b0 + 8192  + dOff + 4096,  pW + d64);
        CPA16(b0 + 16384 + dOff,         pW + dWl);
        CPA16(b0 + 16384 + dOff + 4096,  pW + dWl + d64);
        CPCOMMIT();
    }

    for (int kb = 0; kb < nk; kb++) {
        CPWAIT0();
        __syncthreads();
        if (kb + 1 < nk) {
            int ko = (kb + 1) << 5;
            unsigned b0 = sbase + ((unsigned)((kb + 1) & 1)) * 24576u;
            CPA16(b0 + dOff,                 pA + ko);
            CPA16(b0 + dOff + 4096,          pA + d64 + ko);
            CPA16(b0 + 8192  + dOff,         pW + ko);
            CPA16(b0 + 8192  + dOff + 4096,  pW + d64 + ko);
            CPA16(b0 + 16384 + dOff,         pW + dWl + ko);
            CPA16(b0 + 16384 + dOff + 4096,  pW + dWl + d64 + ko);
            CPCOMMIT();
        }

        unsigned bA = sbase + ((unsigned)(kb & 1)) * 24576u;
        unsigned bWh = bA + 8192, bWl = bA + 16384;

        #pragma unroll
        for (int s = 0; s < 2; s++) {
            unsigned so = s << 5;
            unsigned aA[4][4], bH[2][4], bL[2][4];
            #pragma unroll
            for (int i = 0; i < 4; i++) LDSM4(aA[i], bA + SW64(aOff[i] + so));
            #pragma unroll
            for (int j = 0; j < 2; j++) LDSM4(bH[j], bWh + SW64(bOff[j] + so));
            #pragma unroll
            for (int i = 0; i < 4; i++)
                #pragma unroll
                for (int j = 0; j < 2; j++) {
                    MMA_F16(acc[i][2*j],   aA[i], bH[j][0], bH[j][2]);
                    MMA_F16(acc[i][2*j+1], aA[i], bH[j][1], bH[j][3]);
                }
            #pragma unroll
            for (int j = 0; j < 2; j++) LDSM4(bL[j], bWl + SW64(bOff[j] + so));
            #pragma unroll
            for (int i = 0; i < 4; i++)
                #pragma unroll
                for (int j = 0; j < 2; j++) {
                    MMA_F16(acc[i][2*j],   aA[i], bL[j][0], bL[j][2]);
                    MMA_F16(acc[i][2*j+1], aA[i], bL[j][1], bL[j][3]);
                }
        }
        __syncthreads();
    }

    #pragma unroll
    for (int i = 0; i < 4; i++) {
        #pragma unroll
        for (int j = 0; j < 4; j++) {
            int row0 = bm + m0 + 16 * i + fr;
            int col  = bn + n0 + 8 * j + kp * 2;
            #pragma unroll
            for (int half = 0; half < 2; half++) {
                int row = row0 + half * 8;
                float v0 = acc[i][j][2 * half + 0];
                float v1 = acc[i][j][2 * half + 1];
                size_t off = (size_t)row * N + col;
                if (MODE == 0) {
                    *(float2*)(C + off) = make_float2(v0, v1);
                } else if (MODE == 1) {
                    float2 xr = *(const float2*)(X + off);
                    *(float2*)(C + off) = make_float2(v0 + xr.x, v1 + xr.y);
                } else {
                    float2 gr = *(const float2*)(X + off);
                    v0 *= gr.x / (1.0f + expf(-gr.x));
                    v1 *= gr.y / (1.0f + expf(-gr.y));
                    *(unsigned*)(C16 + off) = pack_h2(v0 * 0.0625f, v1 * 0.0625f);
                }
            }
        }
    }
}

// ---------------- RoPE + bf16 hi/lo split of Q/K/V -> attention planes ----------------
__global__ void rope_split_kernel(const int* __restrict__ pos_ids) {
    int gid = blockIdx.x * blockDim.x + threadIdx.x;
    int d = gid & 31;
    int slot = (gid >> 5) % 56;
    int tok = (gid >> 5) / 56;
    if (tok >= M_TOK) return;
    if (slot < 40) {
        float p = (float)pos_ids[tok];
        float inv = powf(10000.0f, -(float)d * (1.0f / 32.0f));
        float ang = p * inv;
        float s, c;
        sincosf(ang, &s, &c);
        const float* base;
        __nv_bfloat16 *dh, *dl;
        if (slot < NH) {
            base = g_qkv + (size_t)tok * QKV_N + (slot << 6);
            dh = g_qp_h + (size_t)tok * H + (slot << 6);
            dl = g_qp_l + (size_t)tok * H + (slot << 6);
        } else {
            base = g_qkv + (size_t)tok * QKV_N + 2048 + ((slot - NH) << 6);
            dh = g_kp_h + (size_t)tok * 512 + ((slot - NH) << 6);
            dl = g_kp_l + (size_t)tok * 512 + ((slot - NH) << 6);
        }
        float x1 = base[d];
        float x2 = base[d + 32];
        float y1 = x1 * c - x2 * s;
        float y2 = x2 * c + x1 * s;
        if (slot < NH) { y1 *= 0.125f; y2 *= 0.125f; }
        float h1, l1, h2, l2;
        split1(y1, h1, l1);
        split1(y2, h2, l2);
        dh[d]      = __float2bfloat16(h1);
        dl[d]      = __float2bfloat16(l1);
        dh[d + 32] = __float2bfloat16(h2);
        dl[d + 32] = __float2bfloat16(l2);
    } else {
        int e = ((slot - 40) << 5) + d;
        float v = g_qkv[(size_t)tok * QKV_N + 2560 + e];
        float hv, lv;
        split1(v, hv, lv);
        g_vp_h[(size_t)tok * 512 + e] = __float2bfloat16(hv);
        g_vp_l[(size_t)tok * 512 + e] = __float2bfloat16(lv);
    }
}

// ---------------- Tensor-core flash attention (causal, GQA) -> bf16 hi/lo planes ----------------
__global__ void __launch_bounds__(256, 2) attn_kernel() {
    extern __shared__ unsigned char smn[];
    unsigned sb = (unsigned)__cvta_generic_to_shared(smn);
    const unsigned QhO = 0,     QlO = 8192,  KhO = 16384, KlO = 24576;
    const unsigned VhO = 32768, VlO = 40960, PhO = 49152, PlO = 57344;
    float* St   = (float*)(smn + 65536);
    float* corr = (float*)(smn + 82944);
    float* linv = (float*)(smn + 83200);

    int qt = (SEQ / 64 - 1) - blockIdx.x;   // longest-first scheduling
    int h = blockIdx.y, b = blockIdx.z;
    int kh = h >> 2;
    int tid = threadIdx.x, warp = tid >> 5, lane = tid & 31;
    int m0 = (warp >> 1) << 4;
    int n0 = (warp & 1) << 5;
    int lr = lane & 15, lc = lane >> 4;
    int fr = lane >> 2, kp = lane & 3;
    int qr = tid >> 2, qc = tid & 3;

    ptrdiff_t dQl = g_qp_l - g_qp_h;
    ptrdiff_t dKl = g_kp_l - g_kp_h;
    ptrdiff_t dVl = g_vp_l - g_vp_h;

    int sr0 = tid >> 3, sc0 = tid & 7;
    unsigned sOffA = SW128X(sr0 * 128 + sc0 * 16);
    unsigned sOffB = SW128X((sr0 + 32) * 128 + sc0 * 16);

    {
        const __nv_bfloat16* qb = g_qp_h + (size_t)(b * SEQ + (qt << 6) + sr0) * H + (h << 6) + sc0 * 8;
        const __nv_bfloat16* qb2 = qb + (size_t)32 * H;
        *(uint4*)(smn + QhO + sOffA) = *(const uint4*)qb;
        *(uint4*)(smn + QlO + sOffA) = *(const uint4*)(qb + dQl);
        *(uint4*)(smn + QhO + sOffB) = *(const uint4*)qb2;
        *(uint4*)(smn + QlO + sOffB) = *(const uint4*)(qb2 + dQl);
    }

    float oacc[4][4];
    #pragma unroll
    for (int j = 0; j < 4; j++)
        #pragma unroll
        for (int r = 0; r < 4; r++) oacc[j][r] = 0.0f;
    float mrow = -INFINITY, lrow = 0.0f;

    for (int kt = 0; kt <= qt; kt++) {
        __syncthreads();
        int tokbase = b * SEQ + (kt << 6);
        {
            const __nv_bfloat16* kb  = g_kp_h + (size_t)(tokbase + sr0) * 512 + (kh << 6) + sc0 * 8;
            const __nv_bfloat16* kb2 = kb + (size_t)32 * 512;
            const __nv_bfloat16* vb  = g_vp_h + (size_t)(tokbase + sr0) * 512 + (kh << 6) + sc0 * 8;
            const __nv_bfloat16* vb2 = vb + (size_t)32 * 512;
            uint4 k0 = *(const uint4*)kb;
            uint4 k0l = *(const uint4*)(kb + dKl);
            uint4 k1 = *(const uint4*)kb2;
            uint4 k1l = *(const uint4*)(kb2 + dKl);
            uint4 v0 = *(const uint4*)vb;
            uint4 v0l = *(const uint4*)(vb + dVl);
            uint4 v1 = *(const uint4*)vb2;
            uint4 v1l = *(const uint4*)(vb2 + dVl);
            *(uint4*)(smn + KhO + sOffA) = k0;
            *(uint4*)(smn + KlO + sOffA) = k0l;
            *(uint4*)(smn + KhO + sOffB) = k1;
            *(uint4*)(smn + KlO + sOffB) = k1l;
            *(uint4*)(smn + VhO + sOffA) = v0;
            *(uint4*)(smn + VlO + sOffA) = v0l;
            *(uint4*)(smn + VhO + sOffB) = v1;
            *(uint4*)(smn + VlO + sOffB) = v1l;
        }
        __syncthreads();

        float accS[4][4];
        #pragma unroll
        for (int j = 0; j < 4; j++)
            #pragma unroll
            for (int r = 0; r < 4; r++) accS[j][r] = 0.0f;
        #pragma unroll
        for (int ks = 0; ks < 4; ks++) {
            unsigned co = 32*ks + 16*lc;
            unsigned aoff = SW128X((m0 + lr)*128 + co);
            unsigned ah[4], al[4];
            LDSM4(ah, sb + QhO + aoff);
            LDSM4(al, sb + QlO + aoff);
            #pragma unroll
            for (int j2 = 0; j2 < 2; j2++) {
                unsigned boff = SW128X((n0 + 16*j2 + lr)*128 + co);
                unsigned bh[4], bl[4];
                LDSM4(bh, sb + KhO + boff);
                LDSM4(bl, sb + KlO + boff);
                MMA_B16(accS[2*j2],   ah, bh[0], bh[2]);
                MMA_B16(accS[2*j2+1], ah, bh[1], bh[3]);
                MMA_B16(accS[2*j2],   ah, bl[0], bl[2]);
                MMA_B16(accS[2*j2+1], ah, bl[1], bl[3]);
                MMA_B16(accS[2*j2],   al, bh[0], bh[2]);
                MMA_B16(accS[2*j2+1], al, bh[1], bh[3]);
            }
        }
        bool diag = (kt == qt);
        #pragma unroll
        for (int j = 0; j < 4; j++) {
            int col = n0 + 8*j + 2*kp;
            #pragma unroll
            for (int hf = 0; hf < 2; hf++) {
                int row = m0 + fr + 8*hf;
                float v0 = accS[j][2*hf], v1 = accS[j][2*hf+1];
                if (diag) {
                    if (col > row)     v0 = -INFINITY;
                    if (col + 1 > row) v1 = -INFINITY;
                }
                *(float2*)&St[row*68 + col] = make_float2(v0, v1);
            }
        }
        __syncthreads();

        float* srow = &St[qr*68 + (qc<<4)];
        float tmax = -INFINITY;
        #pragma unroll
        for (int j = 0; j < 16; j++) tmax = fmaxf(tmax, srow[j]);
        tmax = fmaxf(tmax, __shfl_xor_sync(0xffffffffu, tmax, 1));
        tmax = fmaxf(tmax, __shfl_xor_sync(0xffffffffu, tmax, 2));
        float mnew = fmaxf(mrow, tmax);
        float cv = __expf(mrow - mnew);
        float psum = 0.0f;
        float pv[16];
        #pragma unroll
        for (int j = 0; j < 16; j++) { pv[j] = __expf(srow[j] - mnew); psum += pv[j]; }
        psum += __shfl_xor_sync(0xffffffffu, psum, 1);
        psum += __shfl_xor_sync(0xffffffffu, psum, 2);
        lrow = lrow * cv + psum;
        mrow = mnew;
        if (qc == 0) corr[qr] = cv;
        #pragma unroll
        for (int p = 0; p < 8; p++) {
            float hh0, ll0, hh1, ll1;
            split1(pv[2*p],   hh0, ll0);
            split1(pv[2*p+1], hh1, ll1);
            unsigned off = SW128X(qr*128 + qc*32 + p*4);
            *(unsigned*)(smn + PhO + off) = pack_bf2(hh0, hh1);
            *(unsigned*)(smn + PlO + off) = pack_bf2(ll0, ll1);
        }
        __syncthreads();

        float c0v = corr[m0 + fr], c1v = corr[m0 + fr + 8];
        #pragma unroll
        for (int j = 0; j < 4; j++) {
            oacc[j][0] *= c0v; oacc[j][1] *= c0v;
            oacc[j][2] *= c1v; oacc[j][3] *= c1v;
        }
        #pragma unroll
        for (int ks = 0; ks < 4; ks++) {
            unsigned co = 32*ks + 16*lc;
            unsigned aoff = SW128X((m0 + lr)*128 + co);
            unsigned ph[4], pl[4];
            LDSM4(ph, sb + PhO + aoff);
            LDSM4(pl, sb + PlO + aoff);
            #pragma unroll
            for (int j2 = 0; j2 < 2; j2++) {
                unsigned boff = SW128X((16*ks + lr)*128 + (n0 + 16*j2)*2 + 16*lc);
                unsigned bh[4], bl[4];
                LDSM4T(bh, sb + VhO + boff);
                LDSM4T(bl, sb + VlO + boff);
                MMA_B16(oacc[2*j2],   ph, bh[0], bh[1]);
                MMA_B16(oacc[2*j2+1], ph, bh[2], bh[3]);
                MMA_B16(oacc[2*j2],   ph, bl[0], bl[1]);
                MMA_B16(oacc[2*j2+1], ph, bl[2], bl[3]);
                MMA_B16(oacc[2*j2],   pl, bh[0], bh[1]);
                MMA_B16(oacc[2*j2+1], pl, bh[2], bh[3]);
            }
        }
    }

    if (qc == 0) linv[qr] = 1.0f / lrow;
    __syncthreads();
    float i0 = linv[m0 + fr], i1 = linv[m0 + fr + 8];
    #pragma unroll
    for (int j = 0; j < 4; j++) {
        int d = n0 + 8*j + 2*kp;
        #pragma unroll
        for (int hf = 0; hf < 2; hf++) {
            int row = m0 + fr + 8*hf;
            float sc = hf ? i1 : i0;
            float v0 = oacc[j][2*hf] * sc, v1 = oacc[j][2*hf+1] * sc;
            float h0, l0, h1, l1;
            split1(v0, h0, l0);
            split1(v1, h1, l1);
            size_t idx = (((size_t)(b*SEQ + (qt<<6) + row)*NH + h) << 6) + d;
            *(unsigned*)(g_ao_h + idx) = pack_bf2(h0, h1);
            *(unsigned*)(g_ao_l + idx) = pack_bf2(l0, l1);
        }
    }
}

// ---------------- launch ----------------
extern "C" void kernel_launch(void* const* d_in, const int* in_sizes, int n_in,
                              void* d_out, int out_size) {
    (void)in_sizes; (void)n_in; (void)out_size;
    const float* hs     = (const float*)d_in[0];
    const int*   pos    = (const int*)d_in[2];
    const float* q_w    = (const float*)d_in[3];
    const float* k_w    = (const float*)d_in[4];
    const float* v_w    = (const float*)d_in[5];
    const float* o_w    = (const float*)d_in[6];
    const float* gate_w = (const float*)d_in[7];
    const float* up_w   = (const float*)d_in[8];
    const float* down_w = (const float*)d_in[9];
    const float* ln1    = (const float*)d_in[10];
    const float* ln2    = (const float*)d_in[11];
    const float* kkp    = (const float*)d_in[12];
    const float* aap    = (const float*)d_in[13];
    float* out = (float*)d_out;

    float *qkv, *hid, *gate;
    __nv_bfloat16 *xnh, *xnl, *aoh, *aol, *wh, *wl;
    __half *w16h, *w16l, *xn16, *act16;
    cudaGetSymbolAddress((void**)&qkv,   g_qkv);
    cudaGetSymbolAddress((void**)&hid,   g_hidden);
    cudaGetSymbolAddress((void**)&gate,  g_gate);
    cudaGetSymbolAddress((void**)&xnh,   g_xn_h);
    cudaGetSymbolAddress((void**)&xnl,   g_xn_l);
    cudaGetSymbolAddress((void**)&aoh,   g_ao_h);
    cudaGetSymbolAddress((void**)&aol,   g_ao_l);
    cudaGetSymbolAddress((void**)&wh,    g_w_h);
    cudaGetSymbolAddress((void**)&wl,    g_w_l);
    cudaGetSymbolAddress((void**)&w16h,  g_w16_h);
    cudaGetSymbolAddress((void**)&w16l,  g_w16_l);
    cudaGetSymbolAddress((void**)&xn16,  g_xn16);
    cudaGetSymbolAddress((void**)&act16, g_act16);

    cudaFuncSetAttribute(attn_kernel, cudaFuncAttributeMaxDynamicSharedMemorySize, ATTN_SMEM);
    cudaFuncSetAttribute(gemm_mma<0>, cudaFuncAttributeMaxDynamicSharedMemorySize, GEMM_SMEM);
    cudaFuncSetAttribute(gemm_mma<1>, cudaFuncAttributeMaxDynamicSharedMemorySize, GEMM_SMEM);
    cudaFuncSetAttribute(gemm_f16<0>, cudaFuncAttributeMaxDynamicSharedMemorySize, GEMM16_SMEM);
    cudaFuncSetAttribute(gemm_f16<1>, cudaFuncAttributeMaxDynamicSharedMemorySize, GEMM16_SMEM);
    cudaFuncSetAttribute(gemm_f16<2>, cudaFuncAttributeMaxDynamicSharedMemorySize, GEMM16_SMEM);

    dim3 blk(256);

    // 0) weight prepass: QKV/O -> bf16 split; MLP -> fp16 split (down pre-scaled x16)
    binsplit_kernel<<<(2048*2048)/1024, blk>>>(q_w, wh + OFF_Q, wl + OFF_Q, kkp, aap);
    binsplit_kernel<<<(512*2048)/1024,  blk>>>(k_w, wh + OFF_K, wl + OFF_K, kkp, aap);
    binsplit_kernel<<<(512*2048)/1024,  blk>>>(v_w, wh + OFF_V, wl + OFF_V, kkp, aap);
    binsplit_kernel<<<(2048*2048)/1024, blk>>>(o_w, wh + OFF_O, wl + OFF_O, kkp, aap);
    binsplit16_kernel<<<(5632*2048)/1024, blk>>>(gate_w, w16h + OFF16_G, w16l + OFF16_G, kkp, aap, 1.0f);
    binsplit16_kernel<<<(5632*2048)/1024, blk>>>(up_w,   w16h + OFF16_U, w16l + OFF16_U, kkp, aap, 1.0f);
    binsplit16_kernel<<<(2048*5632)/1024, blk>>>(down_w, w16h + OFF16_D, w16l + OFF16_D, kkp, aap, 16.0f);

    // 1) rmsnorm 1 -> bf16 planes
    rmsnorm_kernel<<<M_TOK, blk>>>(hs, ln1, xnh, xnl);
    // 2) fused QKV projection (bf16 3-pass)
    gemm_mma<0><<<dim3(QKV_N/128, M_TOK/128), blk, GEMM_SMEM>>>(xnh, xnl, wh+OFF_Q, wl+OFF_Q, nullptr, qkv, QKV_N, H);
    // 3) rope + split -> attention planes
    rope_split_kernel<<<(M_TOK*56*32)/256, blk>>>(pos);
    // 4) attention -> ao planes
    attn_kernel<<<dim3(SEQ/64, NH, BATCH), blk, ATTN_SMEM>>>();
    // 5) o-proj + residual (bf16 3-pass)
    gemm_mma<1><<<dim3(H/128, M_TOK/128), blk, GEMM_SMEM>>>(aoh, aol, wh+OFF_O, wl+OFF_O, hs, hid, H, H);
    // 6) rmsnorm 2 -> fp16 plane
    rmsnorm16_kernel<<<M_TOK, blk>>>(hid, ln2, xn16);
    // 7) gate proj (fp16 2-pass, fp32 out)
    gemm_f16<0><<<dim3(FF/128, M_TOK/128), blk, GEMM16_SMEM>>>(xn16, w16h+OFF16_G, w16l+OFF16_G, nullptr, gate, nullptr, FF, H);
    // 8) up proj, fused silu(gate)*up -> fp16 act (x1/16)
    gemm_f16<2><<<dim3(FF/128, M_TOK/128), blk, GEMM16_SMEM>>>(xn16, w16h+OFF16_U, w16l+OFF16_U, gate, nullptr, act16, FF, H);
    // 9) down proj (weights x16) + residual -> out
    gemm_f16<1><<<dim3(H/128, M_TOK/128), blk, GEMM16_SMEM>>>(act16, w16h+OFF16_D, w16l+OFF16_D, hid, out, nullptr, H, FF);
}

// round 14
// speedup vs baseline: 1.5333x; 1.5333x over previous
#include <cuda_runtime.h>
#include <cuda_bf16.h>
#include <cuda_fp16.h>
#include <math.h>

#define H      2048
#define NH     32
#define NKV    8
#define HD     64
#define GROUPS 4
#define FF     5632
#define BATCH  2
#define SEQ    2048
#define M_TOK  (BATCH*SEQ)
#define QKV_N  3072

#define ATTN_SMEM   83456
#define GEMM_SMEM   65536
#define GEMM16_SMEM 49152

// bf16 weight planes (QKV + O only)
#define OFF_Q  ((size_t)0)
#define OFF_K  (OFF_Q + (size_t)2048*2048)
#define OFF_V  (OFF_K + (size_t)512*2048)
#define OFF_O  (OFF_V + (size_t)512*2048)
#define W_TOTAL (OFF_O + (size_t)2048*2048)
// fp16 weight planes (MLP)
#define OFF16_G ((size_t)0)
#define OFF16_U (OFF16_G + (size_t)5632*2048)
#define OFF16_D (OFF16_U + (size_t)5632*2048)
#define W16_TOTAL (OFF16_D + (size_t)2048*5632)

// ---------------- scratch (device globals: allocation-guard safe) ----------------
__device__ float g_qkv[M_TOK*QKV_N];
__device__ float g_hidden[M_TOK*H];
__device__ float g_gate[M_TOK*FF];
__device__ __nv_bfloat16 g_xn_h[M_TOK*H];
__device__ __nv_bfloat16 g_xn_l[M_TOK*H];
__device__ __nv_bfloat16 g_ao_h[M_TOK*H];
__device__ __nv_bfloat16 g_ao_l[M_TOK*H];
__device__ __nv_bfloat16 g_w_h[W_TOTAL];
__device__ __nv_bfloat16 g_w_l[W_TOTAL];
__device__ __half g_w16_h[W16_TOTAL];
__device__ __half g_w16_l[W16_TOTAL];
__device__ __half g_xn16[M_TOK*H];
__device__ __half g_act16[M_TOK*FF];
// rope'd attention input planes (Q pre-scaled by 1/8)
__device__ __nv_bfloat16 g_qp_h[M_TOK*H];
__device__ __nv_bfloat16 g_qp_l[M_TOK*H];
__device__ __nv_bfloat16 g_kp_h[M_TOK*NKV*HD];
__device__ __nv_bfloat16 g_kp_l[M_TOK*NKV*HD];
__device__ __nv_bfloat16 g_vp_h[M_TOK*NKV*HD];
__device__ __nv_bfloat16 g_vp_l[M_TOK*NKV*HD];

// ---------------- helpers ----------------
__device__ __forceinline__ unsigned pack_bf2(float a, float b) {
    __nv_bfloat162 t = __floats2bfloat162_rn(a, b);
    return *(unsigned*)&t;
}
__device__ __forceinline__ unsigned pack_h2(float a, float b) {
    __half2 t = __floats2half2_rn(a, b);
    return *(unsigned*)&t;
}
__device__ __forceinline__ void split1(float x, float& hi, float& lo) {
    __nv_bfloat16 hb = __float2bfloat16(x);
    hi = __bfloat162float(hb);
    lo = x - hi;
}
__device__ __forceinline__ void split1h(float x, float& hi, float& lo) {
    __half hb = __float2half_rn(x);
    hi = __half2float(hb);
    lo = x - hi;
}

#define SW64(x)   ((unsigned)(x) ^ ((((unsigned)(x)) >> 3) & 0x30u))
#define SW128X(x) ((unsigned)(x) ^ ((((unsigned)(x)) >> 3) & 0x70u))

#define CPA16(dst, src) \
    asm volatile("cp.async.cg.shared.global [%0], [%1], 16;" :: "r"(dst), "l"(src))
#define CPCOMMIT() asm volatile("cp.async.commit_group;")
#define CPWAIT0()  asm volatile("cp.async.wait_group 0;")

#define LDSM4(r, a) \
    asm volatile("ldmatrix.sync.aligned.m8n8.x4.shared.b16 {%0,%1,%2,%3}, [%4];" \
                 : "=r"((r)[0]), "=r"((r)[1]), "=r"((r)[2]), "=r"((r)[3]) : "r"(a))
#define LDSM4T(r, a) \
    asm volatile("ldmatrix.sync.aligned.m8n8.x4.trans.shared.b16 {%0,%1,%2,%3}, [%4];" \
                 : "=r"((r)[0]), "=r"((r)[1]), "=r"((r)[2]), "=r"((r)[3]) : "r"(a))

#define MMA_B16(c, a, b0v, b1v) \
    asm volatile("mma.sync.aligned.m16n8k16.row.col.f32.bf16.bf16.f32 " \
                 "{%0,%1,%2,%3},{%4,%5,%6,%7},{%8,%9},{%0,%1,%2,%3};" \
                 : "+f"((c)[0]), "+f"((c)[1]), "+f"((c)[2]), "+f"((c)[3]) \
                 : "r"((a)[0]), "r"((a)[1]), "r"((a)[2]), "r"((a)[3]), "r"(b0v), "r"(b1v))
#define MMA_F16(c, a, b0v, b1v) \
    asm volatile("mma.sync.aligned.m16n8k16.row.col.f32.f16.f16.f32 " \
                 "{%0,%1,%2,%3},{%4,%5,%6,%7},{%8,%9},{%0,%1,%2,%3};" \
                 : "+f"((c)[0]), "+f"((c)[1]), "+f"((c)[2]), "+f"((c)[3]) \
                 : "r"((a)[0]), "r"((a)[1]), "r"((a)[2]), "r"((a)[3]), "r"(b0v), "r"(b1v))

// ---------------- weight binarize + bf16 hi/lo split prepass ----------------
__global__ void binsplit_kernel(const float* __restrict__ src,
                                __nv_bfloat16* __restrict__ dh,
                                __nv_bfloat16* __restrict__ dl,
                                const float* __restrict__ kkp, const float* __restrict__ aap) {
    const float kk = kkp[0], aa = aap[0];
    size_t i = ((size_t)blockIdx.x * 256 + threadIdx.x) * 4;
    float4 w = *(const float4*)(src + i);
    float v[4] = {w.x, w.y, w.z, w.w};
    float hv[4], lv[4];
    #pragma unroll
    for (int j = 0; j < 4; j++) {
        float b = aa * fminf(fmaxf(kk * v[j], -1.0f), 1.0f);
        split1(b, hv[j], lv[j]);
    }
    *(uint2*)(dh + i) = make_uint2(pack_bf2(hv[0], hv[1]), pack_bf2(hv[2], hv[3]));
    *(uint2*)(dl + i) = make_uint2(pack_bf2(lv[0], lv[1]), pack_bf2(lv[2], lv[3]));
}

// ---------------- weight binarize + fp16 hi/lo split prepass (with output scale) ----------------
__global__ void binsplit16_kernel(const float* __restrict__ src,
                                  __half* __restrict__ dh,
                                  __half* __restrict__ dl,
                                  const float* __restrict__ kkp, const float* __restrict__ aap,
                                  float scale) {
    const float kk = kkp[0], aa = aap[0];
    size_t i = ((size_t)blockIdx.x * 256 + threadIdx.x) * 4;
    float4 w = *(const float4*)(src + i);
    float v[4] = {w.x, w.y, w.z, w.w};
    float hv[4], lv[4];
    #pragma unroll
    for (int j = 0; j < 4; j++) {
        float b = aa * fminf(fmaxf(kk * v[j], -1.0f), 1.0f) * scale;
        split1h(b, hv[j], lv[j]);
    }
    *(uint2*)(dh + i) = make_uint2(pack_h2(hv[0], hv[1]), pack_h2(hv[2], hv[3]));
    *(uint2*)(dl + i) = make_uint2(pack_h2(lv[0], lv[1]), pack_h2(lv[2], lv[3]));
}

// ---------------- RMSNorm -> bf16 hi/lo planes ----------------
__global__ void rmsnorm_kernel(const float* __restrict__ x, const float* __restrict__ w,
                               __nv_bfloat16* __restrict__ yh, __nv_bfloat16* __restrict__ yl) {
    int row = blockIdx.x;
    const float4* xr = (const float4*)(x + (size_t)row * H);
    const float4* wv = (const float4*)w;
    int tid = threadIdx.x;
    float4 a = xr[tid];
    float4 b = xr[tid + 256];
    float ss = a.x*a.x + a.y*a.y + a.z*a.z + a.w*a.w
             + b.x*b.x + b.y*b.y + b.z*b.z + b.w*b.w;
    #pragma unroll
    for (int o = 16; o; o >>= 1) ss += __shfl_xor_sync(0xffffffffu, ss, o);
    __shared__ float ws[8];
    if ((tid & 31) == 0) ws[tid >> 5] = ss;
    __syncthreads();
    float tot = ws[0]+ws[1]+ws[2]+ws[3]+ws[4]+ws[5]+ws[6]+ws[7];
    float r = rsqrtf(tot * (1.0f / (float)H) + 1e-5f);
    float4 w0 = wv[tid], w1 = wv[tid + 256];
    float o0[4] = {a.x*r*w0.x, a.y*r*w0.y, a.z*r*w0.z, a.w*r*w0.w};
    float o1[4] = {b.x*r*w1.x, b.y*r*w1.y, b.z*r*w1.z, b.w*r*w1.w};
    float h0[4], l0[4], h1[4], l1[4];
    #pragma unroll
    for (int j = 0; j < 4; j++) { split1(o0[j], h0[j], l0[j]); split1(o1[j], h1[j], l1[j]); }
    size_t base = (size_t)row * H + 4 * tid;
    *(uint2*)(yh + base)        = make_uint2(pack_bf2(h0[0],h0[1]), pack_bf2(h0[2],h0[3]));
    *(uint2*)(yl + base)        = make_uint2(pack_bf2(l0[0],l0[1]), pack_bf2(l0[2],l0[3]));
    *(uint2*)(yh + base + 1024) = make_uint2(pack_bf2(h1[0],h1[1]), pack_bf2(h1[2],h1[3]));
    *(uint2*)(yl + base + 1024) = make_uint2(pack_bf2(l1[0],l1[1]), pack_bf2(l1[2],l1[3]));
}

// ---------------- RMSNorm -> fp16 single plane ----------------
__global__ void rmsnorm16_kernel(const float* __restrict__ x, const float* __restrict__ w,
                                 __half* __restrict__ y) {
    int row = blockIdx.x;
    const float4* xr = (const float4*)(x + (size_t)row * H);
    const float4* wv = (const float4*)w;
    int tid = threadIdx.x;
    float4 a = xr[tid];
    float4 b = xr[tid + 256];
    float ss = a.x*a.x + a.y*a.y + a.z*a.z + a.w*a.w
             + b.x*b.x + b.y*b.y + b.z*b.z + b.w*b.w;
    #pragma unroll
    for (int o = 16; o; o >>= 1) ss += __shfl_xor_sync(0xffffffffu, ss, o);
    __shared__ float ws[8];
    if ((tid & 31) == 0) ws[tid >> 5] = ss;
    __syncthreads();
    float tot = ws[0]+ws[1]+ws[2]+ws[3]+ws[4]+ws[5]+ws[6]+ws[7];
    float r = rsqrtf(tot * (1.0f / (float)H) + 1e-5f);
    float4 w0 = wv[tid], w1 = wv[tid + 256];
    size_t base = (size_t)row * H + 4 * tid;
    *(uint2*)(y + base)        = make_uint2(pack_h2(a.x*r*w0.x, a.y*r*w0.y), pack_h2(a.z*r*w0.z, a.w*r*w0.w));
    *(uint2*)(y + base + 1024) = make_uint2(pack_h2(b.x*r*w1.x, b.y*r*w1.y), pack_h2(b.z*r*w1.z, b.w*r*w1.w));
}

// ---------------- tensor-core GEMM: 2-stage cp.async, bf16 hi/lo split, 2 CTA/SM ----------------
// MODE 0: C fp32. MODE 1: C = acc + X.
template<int MODE>
__global__ void __launch_bounds__(256, 2) gemm_mma(
    const __nv_bfloat16* __restrict__ Ah, const __nv_bfloat16* __restrict__ Al,
    const __nv_bfloat16* __restrict__ Wh, const __nv_bfloat16* __restrict__ Wl,
    const float* X, float* __restrict__ C,
    int N, int K)
{
    extern __shared__ unsigned char smem[];
    unsigned sbase = (unsigned)__cvta_generic_to_shared(smem);

    int tid = threadIdx.x;
    int bm = blockIdx.y << 7, bn = blockIdx.x << 7;

    int r0 = tid >> 2, c0 = tid & 3;
    const __nv_bfloat16* pA = Ah + (size_t)(bm + r0) * K + c0 * 8;
    const __nv_bfloat16* pW = Wh + (size_t)(bn + r0) * K + c0 * 8;
    ptrdiff_t dAl = Al - Ah;
    ptrdiff_t dWl = Wl - Wh;
    ptrdiff_t d64 = (ptrdiff_t)64 * K;
    unsigned dOff = SW64(64 * r0 + 16 * c0);

    int warp = tid >> 5, lane = tid & 31;
    int m0 = (warp & 1) << 6;
    int n0 = (warp >> 1) << 5;
    int lr = lane & 15;
    int lc = lane >> 4;
    unsigned aOff[4], bOff[2];
    #pragma unroll
    for (int i = 0; i < 4; i++) aOff[i] = 64u * (m0 + 16 * i + lr) + 16u * lc;
    #pragma unroll
    for (int j = 0; j < 2; j++) bOff[j] = 64u * (n0 + 16 * j + lr) + 16u * lc;

    int fr = lane >> 2, kp = lane & 3;

    float acc[4][4][4];
    #pragma unroll
    for (int i = 0; i < 4; i++)
        #pragma unroll
        for (int j = 0; j < 4; j++)
            #pragma unroll
            for (int r = 0; r < 4; r++) acc[i][j][r] = 0.0f;

    int nk = K >> 5;

    {
        unsigned b0 = sbase;
        CPA16(b0 + dOff,                 pA);
        CPA16(b0 + dOff + 4096,          pA + d64);
        CPA16(b0 + 8192  + dOff,         pA + dAl);
        CPA16(b0 + 8192  + dOff + 4096,  pA + dAl + d64);
        CPA16(b0 + 16384 + dOff,         pW);
        CPA16(b0 + 16384 + dOff + 4096,  pW + d64);
        CPA16(b0 + 24576 + dOff,         pW + dWl);
        CPA16(b0 + 24576 + dOff + 4096,  pW + dWl + d64);
        CPCOMMIT();
    }

    for (int kb = 0; kb < nk; kb++) {
        CPWAIT0();
        __syncthreads();
        if (kb + 1 < nk) {
            int ko = (kb + 1) << 5;
            unsigned b0 = sbase + (((kb + 1) & 1) << 15);
            CPA16(b0 + dOff,                 pA + ko);
            CPA16(b0 + dOff + 4096,          pA + d64 + ko);
            CPA16(b0 + 8192  + dOff,         pA + dAl + ko);
            CPA16(b0 + 8192  + dOff + 4096,  pA + dAl + d64 + ko);
            CPA16(b0 + 16384 + dOff,         pW + ko);
            CPA16(b0 + 16384 + dOff + 4096,  pW + d64 + ko);
            CPA16(b0 + 24576 + dOff,         pW + dWl + ko);
            CPA16(b0 + 24576 + dOff + 4096,  pW + dWl + d64 + ko);
            CPCOMMIT();
        }

        unsigned bAh = sbase + ((kb & 1) << 15);
        unsigned bAl = bAh + 8192, bWh = bAh + 16384, bWl = bAh + 24576;

        #pragma unroll
        for (int s = 0; s < 2; s++) {
            unsigned so = s << 5;
            unsigned aH[4][4], aL[4][4], bH[2][4], bL[2][4];
            #pragma unroll
            for (int i = 0; i < 4; i++) LDSM4(aH[i], bAh + SW64(aOff[i] + so));
            #pragma unroll
            for (int j = 0; j < 2; j++) LDSM4(bH[j], bWh + SW64(bOff[j] + so));
            #pragma unroll
            for (int i = 0; i < 4; i++)
                #pragma unroll
                for (int j = 0; j < 2; j++) {
                    MMA_B16(acc[i][2*j],   aH[i], bH[j][0], bH[j][2]);
                    MMA_B16(acc[i][2*j+1], aH[i], bH[j][1], bH[j][3]);
                }
            #pragma unroll
            for (int j = 0; j < 2; j++) LDSM4(bL[j], bWl + SW64(bOff[j] + so));
            #pragma unroll
            for (int i = 0; i < 4; i++)
                #pragma unroll
                for (int j = 0; j < 2; j++) {
                    MMA_B16(acc[i][2*j],   aH[i], bL[j][0], bL[j][2]);
                    MMA_B16(acc[i][2*j+1], aH[i], bL[j][1], bL[j][3]);
                }
            #pragma unroll
            for (int i = 0; i < 4; i++) LDSM4(aL[i], bAl + SW64(aOff[i] + so));
            #pragma unroll
            for (int i = 0; i < 4; i++)
                #pragma unroll
                for (int j = 0; j < 2; j++) {
                    MMA_B16(acc[i][2*j],   aL[i], bH[j][0], bH[j][2]);
                    MMA_B16(acc[i][2*j+1], aL[i], bH[j][1], bH[j][3]);
                }
        }
        __syncthreads();
    }

    #pragma unroll
    for (int i = 0; i < 4; i++) {
        #pragma unroll
        for (int j = 0; j < 4; j++) {
            int row0 = bm + m0 + 16 * i + fr;
            int col  = bn + n0 + 8 * j + kp * 2;
            #pragma unroll
            for (int half = 0; half < 2; half++) {
                int row = row0 + half * 8;
                float v0 = acc[i][j][2 * half + 0];
                float v1 = acc[i][j][2 * half + 1];
                size_t off = (size_t)row * N + col;
                if (MODE == 0) {
                    *(float2*)(C + off) = make_float2(v0, v1);
                } else {
                    float2 xr = *(const float2*)(X + off);
                    *(float2*)(C + off) = make_float2(v0 + xr.x, v1 + xr.y);
                }
            }
        }
    }
}

// ---------------- tensor-core GEMM: fp16 2-pass (A single plane, W hi/lo), 2 CTA/SM ----------------
// MODE 0: C fp32. MODE 1: C = acc + X (fp32). MODE 2: C16 = silu(X)*acc*(1/16) fp16.
template<int MODE>
__global__ void __launch_bounds__(256, 2) gemm_f16(
    const __half* __restrict__ A,
    const __half* __restrict__ Wh_, const __half* __restrict__ Wl_,
    const float* X, float* C, __half* C16,
    int N, int K)
{
    extern __shared__ unsigned char smem[];
    unsigned sbase = (unsigned)__cvta_generic_to_shared(smem);

    int tid = threadIdx.x;
    int bm = blockIdx.y << 7, bn = blockIdx.x << 7;

    int r0 = tid >> 2, c0 = tid & 3;
    const __half* pA = A + (size_t)(bm + r0) * K + c0 * 8;
    const __half* pW = Wh_ + (size_t)(bn + r0) * K + c0 * 8;
    ptrdiff_t dWl = Wl_ - Wh_;
    ptrdiff_t d64 = (ptrdiff_t)64 * K;
    unsigned dOff = SW64(64 * r0 + 16 * c0);

    int warp = tid >> 5, lane = tid & 31;
    int m0 = (warp & 1) << 6;
    int n0 = (warp >> 1) << 5;
    int lr = lane & 15;
    int lc = lane >> 4;
    unsigned aOff[4], bOff[2];
    #pragma unroll
    for (int i = 0; i < 4; i++) aOff[i] = 64u * (m0 + 16 * i + lr) + 16u * lc;
    #pragma unroll
    for (int j = 0; j < 2; j++) bOff[j] = 64u * (n0 + 16 * j + lr) + 16u * lc;

    int fr = lane >> 2, kp = lane & 3;

    float acc[4][4][4];
    #pragma unroll
    for (int i = 0; i < 4; i++)
        #pragma unroll
        for (int j = 0; j < 4; j++)
            #pragma unroll
            for (int r = 0; r < 4; r++) acc[i][j][r] = 0.0f;

    int nk = K >> 5;

    {
        unsigned b0 = sbase;
        CPA16(b0 + dOff,                 pA);
        CPA16(b0 + dOff + 4096,          pA + d64);
        CPA16(b0 + 8192  + dOff,         pW);
        CPA16(b0 + 8192  + dOff + 4096,  pW + d64);
        CPA16(b0 + 16384 + dOff,         pW + dWl);
        CPA16(b0 + 16384 + dOff + 4096,  pW + dWl + d64);
        CPCOMMIT();
    }

    for (int kb = 0; kb < nk; kb++) {
        CPWAIT0();
        __syncthreads();
        if (kb + 1 < nk) {
            int ko = (kb + 1) << 5;
            unsigned b0 = sbase + ((unsigned)((kb + 1) & 1)) * 24576u;
            CPA16(b0 + dOff,                 pA + ko);
            CPA16(b0 + dOff + 4096,          pA + d64 + ko);
            CPA16(b0 + 8192  + dOff,         pW + ko);
            CPA16(b0 + 8192  + dOff + 4096,  pW + d64 + ko);
            CPA16(b0 + 16384 + dOff,         pW + dWl + ko);
            CPA16(b0 + 16384 + dOff + 4096,  pW + dWl + d64 + ko);
            CPCOMMIT();
        }

        unsigned bA = sbase + ((unsigned)(kb & 1)) * 24576u;
        unsigned bWh = bA + 8192, bWl = bA + 16384;

        #pragma unroll
        for (int s = 0; s < 2; s++) {
            unsigned so = s << 5;
            unsigned aA[4][4], bH[2][4], bL[2][4];
            #pragma unroll
            for (int i = 0; i < 4; i++) LDSM4(aA[i], bA + SW64(aOff[i] + so));
            #pragma unroll
            for (int j = 0; j < 2; j++) LDSM4(bH[j], bWh + SW64(bOff[j] + so));
            #pragma unroll
            for (int i = 0; i < 4; i++)
                #pragma unroll
                for (int j = 0; j < 2; j++) {
                    MMA_F16(acc[i][2*j],   aA[i], bH[j][0], bH[j][2]);
                    MMA_F16(acc[i][2*j+1], aA[i], bH[j][1], bH[j][3]);
                }
            #pragma unroll
            for (int j = 0; j < 2; j++) LDSM4(bL[j], bWl + SW64(bOff[j] + so));
            #pragma unroll
            for (int i = 0; i < 4; i++)
                #pragma unroll
                for (int j = 0; j < 2; j++) {
                    MMA_F16(acc[i][2*j],   aA[i], bL[j][0], bL[j][2]);
                    MMA_F16(acc[i][2*j+1], aA[i], bL[j][1], bL[j][3]);
                }
        }
        __syncthreads();
    }

    #pragma unroll
    for (int i = 0; i < 4; i++) {
        #pragma unroll
        for (int j = 0; j < 4; j++) {
            int row0 = bm + m0 + 16 * i + fr;
            int col  = bn + n0 + 8 * j + kp * 2;
            #pragma unroll
            for (int half = 0; half < 2; half++) {
                int row = row0 + half * 8;
                float v0 = acc[i][j][2 * half + 0];
                float v1 = acc[i][j][2 * half + 1];
                size_t off = (size_t)row * N + col;
                if (MODE == 0) {
                    *(float2*)(C + off) = make_float2(v0, v1);
                } else if (MODE == 1) {
                    float2 xr = *(const float2*)(X + off);
                    *(float2*)(C + off) = make_float2(v0 + xr.x, v1 + xr.y);
                } else {
                    float2 gr = *(const float2*)(X + off);
                    v0 *= gr.x / (1.0f + expf(-gr.x));
                    v1 *= gr.y / (1.0f + expf(-gr.y));
                    *(unsigned*)(C16 + off) = pack_h2(v0 * 0.0625f, v1 * 0.0625f);
                }
            }
        }
    }
}

// ---------------- RoPE + bf16 hi/lo split of Q/K/V -> attention planes ----------------
__global__ void rope_split_kernel(const int* __restrict__ pos_ids) {
    int gid = blockIdx.x * blockDim.x + threadIdx.x;
    int d = gid & 31;
    int slot = (gid >> 5) % 56;
    int tok = (gid >> 5) / 56;
    if (tok >= M_TOK) return;
    if (slot < 40) {
        float p = (float)pos_ids[tok];
        float inv = powf(10000.0f, -(float)d * (1.0f / 32.0f));
        float ang = p * inv;
        float s, c;
        sincosf(ang, &s, &c);
        const float* base;
        __nv_bfloat16 *dh, *dl;
        if (slot < NH) {
            base = g_qkv + (size_t)tok * QKV_N + (slot << 6);
            dh = g_qp_h + (size_t)tok * H + (slot << 6);
            dl = g_qp_l + (size_t)tok * H + (slot << 6);
        } else {
            base = g_qkv + (size_t)tok * QKV_N + 2048 + ((slot - NH) << 6);
            dh = g_kp_h + (size_t)tok * 512 + ((slot - NH) << 6);
            dl = g_kp_l + (size_t)tok * 512 + ((slot - NH) << 6);
        }
        float x1 = base[d];
        float x2 = base[d + 32];
        float y1 = x1 * c - x2 * s;
        float y2 = x2 * c + x1 * s;
        if (slot < NH) { y1 *= 0.125f; y2 *= 0.125f; }
        float h1, l1, h2, l2;
        split1(y1, h1, l1);
        split1(y2, h2, l2);
        dh[d]      = __float2bfloat16(h1);
        dl[d]      = __float2bfloat16(l1);
        dh[d + 32] = __float2bfloat16(h2);
        dl[d + 32] = __float2bfloat16(l2);
    } else {
        int e = ((slot - 40) << 5) + d;
        float v = g_qkv[(size_t)tok * QKV_N + 2560 + e];
        float hv, lv;
        split1(v, hv, lv);
        g_vp_h[(size_t)tok * 512 + e] = __float2bfloat16(hv);
        g_vp_l[(size_t)tok * 512 + e] = __float2bfloat16(lv);
    }
}

// ---------------- Tensor-core flash attention (causal, GQA) -> bf16 hi/lo planes ----------------
__global__ void __launch_bounds__(256, 2) attn_kernel() {
    extern __shared__ unsigned char smn[];
    unsigned sb = (unsigned)__cvta_generic_to_shared(smn);
    const unsigned QhO = 0,     QlO = 8192,  KhO = 16384, KlO = 24576;
    const unsigned VhO = 32768, VlO = 40960, PhO = 49152, PlO = 57344;
    float* St   = (float*)(smn + 65536);
    float* corr = (float*)(smn + 82944);
    float* linv = (float*)(smn + 83200);

    int qt = (SEQ / 64 - 1) - blockIdx.x;   // longest-first scheduling
    int h = blockIdx.y, b = blockIdx.z;
    int kh = h >> 2;
    int tid = threadIdx.x, warp = tid >> 5, lane = tid & 31;
    int m0 = (warp >> 1) << 4;
    int n0 = (warp & 1) << 5;
    int lr = lane & 15, lc = lane >> 4;
    int fr = lane >> 2, kp = lane & 3;
    int qr = tid >> 2, qc = tid & 3;

    ptrdiff_t dQl = g_qp_l - g_qp_h;
    ptrdiff_t dKl = g_kp_l - g_kp_h;
    ptrdiff_t dVl = g_vp_l - g_vp_h;

    int sr0 = tid >> 3, sc0 = tid & 7;
    unsigned sOffA = SW128X(sr0 * 128 + sc0 * 16);
    unsigned sOffB = SW128X((sr0 + 32) * 128 + sc0 * 16);

    {
        const __nv_bfloat16* qb = g_qp_h + (size_t)(b * SEQ + (qt << 6) + sr0) * H + (h << 6) + sc0 * 8;
        const __nv_bfloat16* qb2 = qb + (size_t)32 * H;
        *(uint4*)(smn + QhO + sOffA) = *(const uint4*)qb;
        *(uint4*)(smn + QlO + sOffA) = *(const uint4*)(qb + dQl);
        *(uint4*)(smn + QhO + sOffB) = *(const uint4*)qb2;
        *(uint4*)(smn + QlO + sOffB) = *(const uint4*)(qb2 + dQl);
    }

    float oacc[4][4];
    #pragma unroll
    for (int j = 0; j < 4; j++)
        #pragma unroll
        for (int r = 0; r < 4; r++) oacc[j][r] = 0.0f;
    float mrow = -INFINITY, lrow = 0.0f;

    for (int kt = 0; kt <= qt; kt++) {
        __syncthreads();
        int tokbase = b * SEQ + (kt << 6);
        {
            const __nv_bfloat16* kb  = g_kp_h + (size_t)(tokbase + sr0) * 512 + (kh << 6) + sc0 * 8;
            const __nv_bfloat16* kb2 = kb + (size_t)32 * 512;
            const __nv_bfloat16* vb  = g_vp_h + (size_t)(tokbase + sr0) * 512 + (kh << 6) + sc0 * 8;
            const __nv_bfloat16* vb2 = vb + (size_t)32 * 512;
            uint4 k0 = *(const uint4*)kb;
            uint4 k0l = *(const uint4*)(kb + dKl);
            uint4 k1 = *(const uint4*)kb2;
            uint4 k1l = *(const uint4*)(kb2 + dKl);
            uint4 v0 = *(const uint4*)vb;
            uint4 v0l = *(const uint4*)(vb + dVl);
            uint4 v1 = *(const uint4*)vb2;
            uint4 v1l = *(const uint4*)(vb2 + dVl);
            *(uint4*)(smn + KhO + sOffA) = k0;
            *(uint4*)(smn + KlO + sOffA) = k0l;
            *(uint4*)(smn + KhO + sOffB) = k1;
            *(uint4*)(smn + KlO + sOffB) = k1l;
            *(uint4*)(smn + VhO + sOffA) = v0;
            *(uint4*)(smn + VlO + sOffA) = v0l;
            *(uint4*)(smn + VhO + sOffB) = v1;
            *(uint4*)(smn + VlO + sOffB) = v1l;
        }
        __syncthreads();

        float accS[4][4];
        #pragma unroll
        for (int j = 0; j < 4; j++)
            #pragma unroll
            for (int r = 0; r < 4; r++) accS[j][r] = 0.0f;
        #pragma unroll
        for (int ks = 0; ks < 4; ks++) {
            unsigned co = 32*ks + 16*lc;
            unsigned aoff = SW128X((m0 + lr)*128 + co);
            unsigned ah[4], al[4];
            LDSM4(ah, sb + QhO + aoff);
            LDSM4(al, sb + QlO + aoff);
            #pragma unroll
            for (int j2 = 0; j2 < 2; j2++) {
                unsigned boff = SW128X((n0 + 16*j2 + lr)*128 + co);
                unsigned bh[4], bl[4];
                LDSM4(bh, sb + KhO + boff);
                LDSM4(bl, sb + KlO + boff);
                MMA_B16(accS[2*j2],   ah, bh[0], bh[2]);
                MMA_B16(accS[2*j2+1], ah, bh[1], bh[3]);
                MMA_B16(accS[2*j2],   ah, bl[0], bl[2]);
                MMA_B16(accS[2*j2+1], ah, bl[1], bl[3]);
                MMA_B16(accS[2*j2],   al, bh[0], bh[2]);
                MMA_B16(accS[2*j2+1], al, bh[1], bh[3]);
            }
        }
        bool diag = (kt == qt);
        #pragma unroll
        for (int j = 0; j < 4; j++) {
            int col = n0 + 8*j + 2*kp;
            #pragma unroll
            for (int hf = 0; hf < 2; hf++) {
                int row = m0 + fr + 8*hf;
                float v0 = accS[j][2*hf], v1 = accS[j][2*hf+1];
                if (diag) {
                    if (col > row)     v0 = -INFINITY;
                    if (col + 1 > row) v1 = -INFINITY;
                }
                *(float2*)&St[row*68 + col] = make_float2(v0, v1);
            }
        }
        __syncthreads();

        float* srow = &St[qr*68 + (qc<<4)];
        float tmax = -INFINITY;
        #pragma unroll
        for (int j = 0; j < 16; j++) tmax = fmaxf(tmax, srow[j]);
        tmax = fmaxf(tmax, __shfl_xor_sync(0xffffffffu, tmax, 1));
        tmax = fmaxf(tmax, __shfl_xor_sync(0xffffffffu, tmax, 2));
        float mnew = fmaxf(mrow, tmax);
        float cv = __expf(mrow - mnew);
        float psum = 0.0f;
        float pv[16];
        #pragma unroll
        for (int j = 0; j < 16; j++) { pv[j] = __expf(srow[j] - mnew); psum += pv[j]; }
        psum += __shfl_xor_sync(0xffffffffu, psum, 1);
        psum += __shfl_xor_sync(0xffffffffu, psum, 2);
        lrow = lrow * cv + psum;
        mrow = mnew;
        if (qc == 0) corr[qr] = cv;
        #pragma unroll
        for (int p = 0; p < 8; p++) {
            float hh0, ll0, hh1, ll1;
            split1(pv[2*p],   hh0, ll0);
            split1(pv[2*p+1], hh1, ll1);
            unsigned off = SW128X(qr*128 + qc*32 + p*4);
            *(unsigned*)(smn + PhO + off) = pack_bf2(hh0, hh1);
            *(unsigned*)(smn + PlO + off) = pack_bf2(ll0, ll1);
        }
        __syncthreads();

        float c0v = corr[m0 + fr], c1v = corr[m0 + fr + 8];
        #pragma unroll
        for (int j = 0; j < 4; j++) {
            oacc[j][0] *= c0v; oacc[j][1] *= c0v;
            oacc[j][2] *= c1v; oacc[j][3] *= c1v;
        }
        #pragma unroll
        for (int ks = 0; ks < 4; ks++) {
            unsigned co = 32*ks + 16*lc;
            unsigned aoff = SW128X((m0 + lr)*128 + co);
            unsigned ph[4], pl[4];
            LDSM4(ph, sb + PhO + aoff);
            LDSM4(pl, sb + PlO + aoff);
            #pragma unroll
            for (int j2 = 0; j2 < 2; j2++) {
                unsigned boff = SW128X((16*ks + lr)*128 + (n0 + 16*j2)*2 + 16*lc);
                unsigned bh[4], bl[4];
                LDSM4T(bh, sb + VhO + boff);
                LDSM4T(bl, sb + VlO + boff);
                MMA_B16(oacc[2*j2],   ph, bh[0], bh[1]);
                MMA_B16(oacc[2*j2+1], ph, bh[2], bh[3]);
                MMA_B16(oacc[2*j2],   ph, bl[0], bl[1]);
                MMA_B16(oacc[2*j2+1], ph, bl[2], bl[3]);
                MMA_B16(oacc[2*j2],   pl, bh[0], bh[1]);
                MMA_B16(oacc[2*j2+1], pl, bh[2], bh[3]);
            }
        }
    }

    if (qc == 0) linv[qr] = 1.0f / lrow;
    __syncthreads();
    float i0 = linv[m0 + fr], i1 = linv[m0 + fr + 8];
    #pragma unroll
    for (int j = 0; j < 4; j++) {
        int d = n0 + 8*j + 2*kp;
        #pragma unroll
        for (int hf = 0; hf < 2; hf++) {
            int row = m0 + fr + 8*hf;
            float sc = hf ? i1 : i0;
            float v0 = oacc[j][2*hf] * sc, v1 = oacc[j][2*hf+1] * sc;
            float h0, l0, h1, l1;
            split1(v0, h0, l0);
            split1(v1, h1, l1);
            size_t idx = (((size_t)(b*SEQ + (qt<<6) + row)*NH + h) << 6) + d;
            *(unsigned*)(g_ao_h + idx) = pack_bf2(h0, h1);
            *(unsigned*)(g_ao_l + idx) = pack_bf2(l0, l1);
        }
    }
}

// ---------------- launch ----------------
extern "C" void kernel_launch(void* const* d_in, const int* in_sizes, int n_in,
                              void* d_out, int out_size) {
    (void)in_sizes; (void)n_in; (void)out_size;
    const float* hs     = (const float*)d_in[0];
    const int*   pos    = (const int*)d_in[2];
    const float* q_w    = (const float*)d_in[3];
    const float* k_w    = (const float*)d_in[4];
    const float* v_w    = (const float*)d_in[5];
    const float* o_w    = (const float*)d_in[6];
    const float* gate_w = (const float*)d_in[7];
    const float* up_w   = (const float*)d_in[8];
    const float* down_w = (const float*)d_in[9];
    const float* ln1    = (const float*)d_in[10];
    const float* ln2    = (const float*)d_in[11];
    const float* kkp    = (const float*)d_in[12];
    const float* aap    = (const float*)d_in[13];
    float* out = (float*)d_out;

    float *qkv, *hid, *gate;
    __nv_bfloat16 *xnh, *xnl, *aoh, *aol, *wh, *wl;
    __half *w16h, *w16l, *xn16, *act16;
    cudaGetSymbolAddress((void**)&qkv,   g_qkv);
    cudaGetSymbolAddress((void**)&hid,   g_hidden);
    cudaGetSymbolAddress((void**)&gate,  g_gate);
    cudaGetSymbolAddress((void**)&xnh,   g_xn_h);
    cudaGetSymbolAddress((void**)&xnl,   g_xn_l);
    cudaGetSymbolAddress((void**)&aoh,   g_ao_h);
    cudaGetSymbolAddress((void**)&aol,   g_ao_l);
    cudaGetSymbolAddress((void**)&wh,    g_w_h);
    cudaGetSymbolAddress((void**)&wl,    g_w_l);
    cudaGetSymbolAddress((void**)&w16h,  g_w16_h);
    cudaGetSymbolAddress((void**)&w16l,  g_w16_l);
    cudaGetSymbolAddress((void**)&xn16,  g_xn16);
    cudaGetSymbolAddress((void**)&act16, g_act16);

    cudaFuncSetAttribute(attn_kernel, cudaFuncAttributeMaxDynamicSharedMemorySize, ATTN_SMEM);
    cudaFuncSetAttribute(gemm_mma<0>, cudaFuncAttributeMaxDynamicSharedMemorySize, GEMM_SMEM);
    cudaFuncSetAttribute(gemm_mma<1>, cudaFuncAttributeMaxDynamicSharedMemorySize, GEMM_SMEM);
    cudaFuncSetAttribute(gemm_f16<0>, cudaFuncAttributeMaxDynamicSharedMemorySize, GEMM16_SMEM);
    cudaFuncSetAttribute(gemm_f16<1>, cudaFuncAttributeMaxDynamicSharedMemorySize, GEMM16_SMEM);
    cudaFuncSetAttribute(gemm_f16<2>, cudaFuncAttributeMaxDynamicSharedMemorySize, GEMM16_SMEM);

    dim3 blk(256);

    // 0) weight prepass: QKV/O -> bf16 split; MLP -> fp16 split (down pre-scaled x16)
    binsplit_kernel<<<(2048*2048)/1024, blk>>>(q_w, wh + OFF_Q, wl + OFF_Q, kkp, aap);
    binsplit_kernel<<<(512*2048)/1024,  blk>>>(k_w, wh + OFF_K, wl + OFF_K, kkp, aap);
    binsplit_kernel<<<(512*2048)/1024,  blk>>>(v_w, wh + OFF_V, wl + OFF_V, kkp, aap);
    binsplit_kernel<<<(2048*2048)/1024, blk>>>(o_w, wh + OFF_O, wl + OFF_O, kkp, aap);
    binsplit16_kernel<<<(5632*2048)/1024, blk>>>(gate_w, w16h + OFF16_G, w16l + OFF16_G, kkp, aap, 1.0f);
    binsplit16_kernel<<<(5632*2048)/1024, blk>>>(up_w,   w16h + OFF16_U, w16l + OFF16_U, kkp, aap, 1.0f);
    binsplit16_kernel<<<(2048*5632)/1024, blk>>>(down_w, w16h + OFF16_D, w16l + OFF16_D, kkp, aap, 16.0f);

    // 1) rmsnorm 1 -> bf16 planes
    rmsnorm_kernel<<<M_TOK, blk>>>(hs, ln1, xnh, xnl);
    // 2) fused QKV projection (bf16 3-pass)
    gemm_mma<0><<<dim3(QKV_N/128, M_TOK/128), blk, GEMM_SMEM>>>(xnh, xnl, wh+OFF_Q, wl+OFF_Q, nullptr, qkv, QKV_N, H);
    // 3) rope + split -> attention planes
    rope_split_kernel<<<(M_TOK*56*32)/256, blk>>>(pos);
    // 4) attention -> ao planes
    attn_kernel<<<dim3(SEQ/64, NH, BATCH), blk, ATTN_SMEM>>>();
    // 5) o-proj + residual (bf16 3-pass)
    gemm_mma<1><<<dim3(H/128, M_TOK/128), blk, GEMM_SMEM>>>(aoh, aol, wh+OFF_O, wl+OFF_O, hs, hid, H, H);
    // 6) rmsnorm 2 -> fp16 plane
    rmsnorm16_kernel<<<M_TOK, blk>>>(hid, ln2, xn16);
    // 7) gate proj (fp16 2-pass, fp32 out)
    gemm_f16<0><<<dim3(FF/128, M_TOK/128), blk, GEMM16_SMEM>>>(xn16, w16h+OFF16_G, w16l+OFF16_G, nullptr, gate, nullptr, FF, H);
    // 8) up proj, fused silu(gate)*up -> fp16 act (x1/16)
    gemm_f16<2><<<dim3(FF/128, M_TOK/128), blk, GEMM16_SMEM>>>(xn16, w16h+OFF16_U, w16l+OFF16_U, gate, nullptr, act16, FF, H);
    // 9) down proj (weights x16) + residual -> out
    gemm_f16<1><<<dim3(H/128, M_TOK/128), blk, GEMM16_SMEM>>>(act16, w16h+OFF16_D, w16l+OFF16_D, hid, out, nullptr, H, FF);
}

// round 15
// speedup vs baseline: 1.6399x; 1.0695x over previous
#include <cuda_runtime.h>
#include <cuda_bf16.h>
#include <cuda_fp16.h>
#include <math.h>

#define H      2048
#define NH     32
#define NKV    8
#define HD     64
#define GROUPS 4
#define FF     5632
#define BATCH  2
#define SEQ    2048
#define M_TOK  (BATCH*SEQ)
#define QKV_N  3072

#define ATTN_SMEM   75264
#define GEMM_SMEM   65536
#define GEMM16_SMEM 49152

// bf16 weight planes (QKV only)
#define OFF_Q  ((size_t)0)
#define OFF_K  (OFF_Q + (size_t)2048*2048)
#define OFF_V  (OFF_K + (size_t)512*2048)
#define W_TOTAL (OFF_V + (size_t)512*2048)
// fp16 weight planes (O + MLP)
#define OFF16_O ((size_t)0)
#define OFF16_G (OFF16_O + (size_t)2048*2048)
#define OFF16_U (OFF16_G + (size_t)5632*2048)
#define OFF16_D (OFF16_U + (size_t)5632*2048)
#define W16_TOTAL (OFF16_D + (size_t)2048*5632)

// ---------------- scratch (device globals: allocation-guard safe) ----------------
__device__ float g_qkv[M_TOK*QKV_N];
__device__ float g_hidden[M_TOK*H];
__device__ float g_gate[M_TOK*FF];
__device__ __nv_bfloat16 g_xn_h[M_TOK*H];
__device__ __nv_bfloat16 g_xn_l[M_TOK*H];
__device__ __nv_bfloat16 g_w_h[W_TOTAL];
__device__ __nv_bfloat16 g_w_l[W_TOTAL];
__device__ __half g_w16_h[W16_TOTAL];
__device__ __half g_w16_l[W16_TOTAL];
__device__ __half g_xn16[M_TOK*H];
__device__ __half g_act16[M_TOK*FF];
__device__ __half g_ao16[M_TOK*H];          // attention output, fp16 single plane
// rope'd attention input planes (Q pre-scaled by 1/8); Q/K bf16, V fp16
__device__ __nv_bfloat16 g_qp_h[M_TOK*H];
__device__ __nv_bfloat16 g_qp_l[M_TOK*H];
__device__ __nv_bfloat16 g_kp_h[M_TOK*NKV*HD];
__device__ __nv_bfloat16 g_kp_l[M_TOK*NKV*HD];
__device__ __half g_vp_h[M_TOK*NKV*HD];
__device__ __half g_vp_l[M_TOK*NKV*HD];

// ---------------- helpers ----------------
__device__ __forceinline__ unsigned pack_bf2(float a, float b) {
    __nv_bfloat162 t = __floats2bfloat162_rn(a, b);
    return *(unsigned*)&t;
}
__device__ __forceinline__ unsigned pack_h2(float a, float b) {
    __half2 t = __floats2half2_rn(a, b);
    return *(unsigned*)&t;
}
__device__ __forceinline__ void split1(float x, float& hi, float& lo) {
    __nv_bfloat16 hb = __float2bfloat16(x);
    hi = __bfloat162float(hb);
    lo = x - hi;
}
__device__ __forceinline__ void split1h(float x, float& hi, float& lo) {
    __half hb = __float2half_rn(x);
    hi = __half2float(hb);
    lo = x - hi;
}

#define SW64(x)   ((unsigned)(x) ^ ((((unsigned)(x)) >> 3) & 0x30u))
#define SW128X(x) ((unsigned)(x) ^ ((((unsigned)(x)) >> 3) & 0x70u))

#define CPA16(dst, src) \
    asm volatile("cp.async.cg.shared.global [%0], [%1], 16;" :: "r"(dst), "l"(src))
#define CPCOMMIT() asm volatile("cp.async.commit_group;")
#define CPWAIT0()  asm volatile("cp.async.wait_group 0;")

#define LDSM4(r, a) \
    asm volatile("ldmatrix.sync.aligned.m8n8.x4.shared.b16 {%0,%1,%2,%3}, [%4];" \
                 : "=r"((r)[0]), "=r"((r)[1]), "=r"((r)[2]), "=r"((r)[3]) : "r"(a))
#define LDSM4T(r, a) \
    asm volatile("ldmatrix.sync.aligned.m8n8.x4.trans.shared.b16 {%0,%1,%2,%3}, [%4];" \
                 : "=r"((r)[0]), "=r"((r)[1]), "=r"((r)[2]), "=r"((r)[3]) : "r"(a))

#define MMA_B16(c, a, b0v, b1v) \
    asm volatile("mma.sync.aligned.m16n8k16.row.col.f32.bf16.bf16.f32 " \
                 "{%0,%1,%2,%3},{%4,%5,%6,%7},{%8,%9},{%0,%1,%2,%3};" \
                 : "+f"((c)[0]), "+f"((c)[1]), "+f"((c)[2]), "+f"((c)[3]) \
                 : "r"((a)[0]), "r"((a)[1]), "r"((a)[2]), "r"((a)[3]), "r"(b0v), "r"(b1v))
#define MMA_F16(c, a, b0v, b1v) \
    asm volatile("mma.sync.aligned.m16n8k16.row.col.f32.f16.f16.f32 " \
                 "{%0,%1,%2,%3},{%4,%5,%6,%7},{%8,%9},{%0,%1,%2,%3};" \
                 : "+f"((c)[0]), "+f"((c)[1]), "+f"((c)[2]), "+f"((c)[3]) \
                 : "r"((a)[0]), "r"((a)[1]), "r"((a)[2]), "r"((a)[3]), "r"(b0v), "r"(b1v))

// ---------------- weight binarize + bf16 hi/lo split prepass ----------------
__global__ void binsplit_kernel(const float* __restrict__ src,
                                __nv_bfloat16* __restrict__ dh,
                                __nv_bfloat16* __restrict__ dl,
                                const float* __restrict__ kkp, const float* __restrict__ aap) {
    const float kk = kkp[0], aa = aap[0];
    size_t i = ((size_t)blockIdx.x * 256 + threadIdx.x) * 4;
    float4 w = *(const float4*)(src + i);
    float v[4] = {w.x, w.y, w.z, w.w};
    float hv[4], lv[4];
    #pragma unroll
    for (int j = 0; j < 4; j++) {
        float b = aa * fminf(fmaxf(kk * v[j], -1.0f), 1.0f);
        split1(b, hv[j], lv[j]);
    }
    *(uint2*)(dh + i) = make_uint2(pack_bf2(hv[0], hv[1]), pack_bf2(hv[2], hv[3]));
    *(uint2*)(dl + i) = make_uint2(pack_bf2(lv[0], lv[1]), pack_bf2(lv[2], lv[3]));
}

// ---------------- weight binarize + fp16 hi/lo split prepass (with output scale) ----------------
__global__ void binsplit16_kernel(const float* __restrict__ src,
                                  __half* __restrict__ dh,
                                  __half* __restrict__ dl,
                                  const float* __restrict__ kkp, const float* __restrict__ aap,
                                  float scale) {
    const float kk = kkp[0], aa = aap[0];
    size_t i = ((size_t)blockIdx.x * 256 + threadIdx.x) * 4;
    float4 w = *(const float4*)(src + i);
    float v[4] = {w.x, w.y, w.z, w.w};
    float hv[4], lv[4];
    #pragma unroll
    for (int j = 0; j < 4; j++) {
        float b = aa * fminf(fmaxf(kk * v[j], -1.0f), 1.0f) * scale;
        split1h(b, hv[j], lv[j]);
    }
    *(uint2*)(dh + i) = make_uint2(pack_h2(hv[0], hv[1]), pack_h2(hv[2], hv[3]));
    *(uint2*)(dl + i) = make_uint2(pack_h2(lv[0], lv[1]), pack_h2(lv[2], lv[3]));
}

// ---------------- RMSNorm -> bf16 hi/lo planes ----------------
__global__ void rmsnorm_kernel(const float* __restrict__ x, const float* __restrict__ w,
                               __nv_bfloat16* __restrict__ yh, __nv_bfloat16* __restrict__ yl) {
    int row = blockIdx.x;
    const float4* xr = (const float4*)(x + (size_t)row * H);
    const float4* wv = (const float4*)w;
    int tid = threadIdx.x;
    float4 a = xr[tid];
    float4 b = xr[tid + 256];
    float ss = a.x*a.x + a.y*a.y + a.z*a.z + a.w*a.w
             + b.x*b.x + b.y*b.y + b.z*b.z + b.w*b.w;
    #pragma unroll
    for (int o = 16; o; o >>= 1) ss += __shfl_xor_sync(0xffffffffu, ss, o);
    __shared__ float ws[8];
    if ((tid & 31) == 0) ws[tid >> 5] = ss;
    __syncthreads();
    float tot = ws[0]+ws[1]+ws[2]+ws[3]+ws[4]+ws[5]+ws[6]+ws[7];
    float r = rsqrtf(tot * (1.0f / (float)H) + 1e-5f);
    float4 w0 = wv[tid], w1 = wv[tid + 256];
    float o0[4] = {a.x*r*w0.x, a.y*r*w0.y, a.z*r*w0.z, a.w*r*w0.w};
    float o1[4] = {b.x*r*w1.x, b.y*r*w1.y, b.z*r*w1.z, b.w*r*w1.w};
    float h0[4], l0[4], h1[4], l1[4];
    #pragma unroll
    for (int j = 0; j < 4; j++) { split1(o0[j], h0[j], l0[j]); split1(o1[j], h1[j], l1[j]); }
    size_t base = (size_t)row * H + 4 * tid;
    *(uint2*)(yh + base)        = make_uint2(pack_bf2(h0[0],h0[1]), pack_bf2(h0[2],h0[3]));
    *(uint2*)(yl + base)        = make_uint2(pack_bf2(l0[0],l0[1]), pack_bf2(l0[2],l0[3]));
    *(uint2*)(yh + base + 1024) = make_uint2(pack_bf2(h1[0],h1[1]), pack_bf2(h1[2],h1[3]));
    *(uint2*)(yl + base + 1024) = make_uint2(pack_bf2(l1[0],l1[1]), pack_bf2(l1[2],l1[3]));
}

// ---------------- RMSNorm -> fp16 single plane ----------------
__global__ void rmsnorm16_kernel(const float* __restrict__ x, const float* __restrict__ w,
                                 __half* __restrict__ y) {
    int row = blockIdx.x;
    const float4* xr = (const float4*)(x + (size_t)row * H);
    const float4* wv = (const float4*)w;
    int tid = threadIdx.x;
    float4 a = xr[tid];
    float4 b = xr[tid + 256];
    float ss = a.x*a.x + a.y*a.y + a.z*a.z + a.w*a.w
             + b.x*b.x + b.y*b.y + b.z*b.z + b.w*b.w;
    #pragma unroll
    for (int o = 16; o; o >>= 1) ss += __shfl_xor_sync(0xffffffffu, ss, o);
    __shared__ float ws[8];
    if ((tid & 31) == 0) ws[tid >> 5] = ss;
    __syncthreads();
    float tot = ws[0]+ws[1]+ws[2]+ws[3]+ws[4]+ws[5]+ws[6]+ws[7];
    float r = rsqrtf(tot * (1.0f / (float)H) + 1e-5f);
    float4 w0 = wv[tid], w1 = wv[tid + 256];
    size_t base = (size_t)row * H + 4 * tid;
    *(uint2*)(y + base)        = make_uint2(pack_h2(a.x*r*w0.x, a.y*r*w0.y), pack_h2(a.z*r*w0.z, a.w*r*w0.w));
    *(uint2*)(y + base + 1024) = make_uint2(pack_h2(b.x*r*w1.x, b.y*r*w1.y), pack_h2(b.z*r*w1.z, b.w*r*w1.w));
}

// ---------------- tensor-core GEMM: bf16 3-pass (QKV projection) ----------------
__global__ void __launch_bounds__(256, 2) gemm_mma(
    const __nv_bfloat16* __restrict__ Ah, const __nv_bfloat16* __restrict__ Al,
    const __nv_bfloat16* __restrict__ Wh, const __nv_bfloat16* __restrict__ Wl,
    float* __restrict__ C, int N, int K)
{
    extern __shared__ unsigned char smem[];
    unsigned sbase = (unsigned)__cvta_generic_to_shared(smem);

    int tid = threadIdx.x;
    int bm = blockIdx.y << 7, bn = blockIdx.x << 7;

    int r0 = tid >> 2, c0 = tid & 3;
    const __nv_bfloat16* pA = Ah + (size_t)(bm + r0) * K + c0 * 8;
    const __nv_bfloat16* pW = Wh + (size_t)(bn + r0) * K + c0 * 8;
    ptrdiff_t dAl = Al - Ah;
    ptrdiff_t dWl = Wl - Wh;
    ptrdiff_t d64 = (ptrdiff_t)64 * K;
    unsigned dOff = SW64(64 * r0 + 16 * c0);

    int warp = tid >> 5, lane = tid & 31;
    int m0 = (warp & 1) << 6;
    int n0 = (warp >> 1) << 5;
    int lr = lane & 15;
    int lc = lane >> 4;
    unsigned aOff[4], bOff[2];
    #pragma unroll
    for (int i = 0; i < 4; i++) aOff[i] = 64u * (m0 + 16 * i + lr) + 16u * lc;
    #pragma unroll
    for (int j = 0; j < 2; j++) bOff[j] = 64u * (n0 + 16 * j + lr) + 16u * lc;

    int fr = lane >> 2, kp = lane & 3;

    float acc[4][4][4];
    #pragma unroll
    for (int i = 0; i < 4; i++)
        #pragma unroll
        for (int j = 0; j < 4; j++)
            #pragma unroll
            for (int r = 0; r < 4; r++) acc[i][j][r] = 0.0f;

    int nk = K >> 5;

    {
        unsigned b0 = sbase;
        CPA16(b0 + dOff,                 pA);
        CPA16(b0 + dOff + 4096,          pA + d64);
        CPA16(b0 + 8192  + dOff,         pA + dAl);
        CPA16(b0 + 8192  + dOff + 4096,  pA + dAl + d64);
        CPA16(b0 + 16384 + dOff,         pW);
        CPA16(b0 + 16384 + dOff + 4096,  pW + d64);
        CPA16(b0 + 24576 + dOff,         pW + dWl);
        CPA16(b0 + 24576 + dOff + 4096,  pW + dWl + d64);
        CPCOMMIT();
    }

    for (int kb = 0; kb < nk; kb++) {
        CPWAIT0();
        __syncthreads();
        if (kb + 1 < nk) {
            int ko = (kb + 1) << 5;
            unsigned b0 = sbase + (((kb + 1) & 1) << 15);
            CPA16(b0 + dOff,                 pA + ko);
            CPA16(b0 + dOff + 4096,          pA + d64 + ko);
            CPA16(b0 + 8192  + dOff,         pA + dAl + ko);
            CPA16(b0 + 8192  + dOff + 4096,  pA + dAl + d64 + ko);
            CPA16(b0 + 16384 + dOff,         pW + ko);
            CPA16(b0 + 16384 + dOff + 4096,  pW + d64 + ko);
            CPA16(b0 + 24576 + dOff,         pW + dWl + ko);
            CPA16(b0 + 24576 + dOff + 4096,  pW + dWl + d64 + ko);
            CPCOMMIT();
        }

        unsigned bAh = sbase + ((kb & 1) << 15);
        unsigned bAl = bAh + 8192, bWh = bAh + 16384, bWl = bAh + 24576;

        #pragma unroll
        for (int s = 0; s < 2; s++) {
            unsigned so = s << 5;
            unsigned aH[4][4], aL[4][4], bH[2][4], bL[2][4];
            #pragma unroll
            for (int i = 0; i < 4; i++) LDSM4(aH[i], bAh + SW64(aOff[i] + so));
            #pragma unroll
            for (int j = 0; j < 2; j++) LDSM4(bH[j], bWh + SW64(bOff[j] + so));
            #pragma unroll
            for (int i = 0; i < 4; i++)
                #pragma unroll
                for (int j = 0; j < 2; j++) {
                    MMA_B16(acc[i][2*j],   aH[i], bH[j][0], bH[j][2]);
                    MMA_B16(acc[i][2*j+1], aH[i], bH[j][1], bH[j][3]);
                }
            #pragma unroll
            for (int j = 0; j < 2; j++) LDSM4(bL[j], bWl + SW64(bOff[j] + so));
            #pragma unroll
            for (int i = 0; i < 4; i++)
                #pragma unroll
                for (int j = 0; j < 2; j++) {
                    MMA_B16(acc[i][2*j],   aH[i], bL[j][0], bL[j][2]);
                    MMA_B16(acc[i][2*j+1], aH[i], bL[j][1], bL[j][3]);
                }
            #pragma unroll
            for (int i = 0; i < 4; i++) LDSM4(aL[i], bAl + SW64(aOff[i] + so));
            #pragma unroll
            for (int i = 0; i < 4; i++)
                #pragma unroll
                for (int j = 0; j < 2; j++) {
                    MMA_B16(acc[i][2*j],   aL[i], bH[j][0], bH[j][2]);
                    MMA_B16(acc[i][2*j+1], aL[i], bH[j][1], bH[j][3]);
                }
        }
        __syncthreads();
    }

    #pragma unroll
    for (int i = 0; i < 4; i++) {
        #pragma unroll
        for (int j = 0; j < 4; j++) {
            int row0 = bm + m0 + 16 * i + fr;
            int col  = bn + n0 + 8 * j + kp * 2;
            #pragma unroll
            for (int half = 0; half < 2; half++) {
                int row = row0 + half * 8;
                size_t off = (size_t)row * N + col;
                *(float2*)(C + off) = make_float2(acc[i][j][2*half], acc[i][j][2*half+1]);
            }
        }
    }
}

// ---------------- tensor-core GEMM: fp16 2-pass (A single plane, W hi/lo), 2 CTA/SM ----------------
// MODE 0: C fp32. MODE 1: C = acc + X (fp32). MODE 2: C16 = silu(X)*acc*(1/16) fp16.
template<int MODE>
__global__ void __launch_bounds__(256, 2) gemm_f16(
    const __half* __restrict__ A,
    const __half* __restrict__ Wh_, const __half* __restrict__ Wl_,
    const float* X, float* C, __half* C16,
    int N, int K)
{
    extern __shared__ unsigned char smem[];
    unsigned sbase = (unsigned)__cvta_generic_to_shared(smem);

    int tid = threadIdx.x;
    int bm = blockIdx.y << 7, bn = blockIdx.x << 7;

    int r0 = tid >> 2, c0 = tid & 3;
    const __half* pA = A + (size_t)(bm + r0) * K + c0 * 8;
    const __half* pW = Wh_ + (size_t)(bn + r0) * K + c0 * 8;
    ptrdiff_t dWl = Wl_ - Wh_;
    ptrdiff_t d64 = (ptrdiff_t)64 * K;
    unsigned dOff = SW64(64 * r0 + 16 * c0);

    int warp = tid >> 5, lane = tid & 31;
    int m0 = (warp & 1) << 6;
    int n0 = (warp >> 1) << 5;
    int lr = lane & 15;
    int lc = lane >> 4;
    unsigned aOff[4], bOff[2];
    #pragma unroll
    for (int i = 0; i < 4; i++) aOff[i] = 64u * (m0 + 16 * i + lr) + 16u * lc;
    #pragma unroll
    for (int j = 0; j < 2; j++) bOff[j] = 64u * (n0 + 16 * j + lr) + 16u * lc;

    int fr = lane >> 2, kp = lane & 3;

    float acc[4][4][4];
    #pragma unroll
    for (int i = 0; i < 4; i++)
        #pragma unroll
        for (int j = 0; j < 4; j++)
            #pragma unroll
            for (int r = 0; r < 4; r++) acc[i][j][r] = 0.0f;

    int nk = K >> 5;

    {
        unsigned b0 = sbase;
        CPA16(b0 + dOff,                 pA);
        CPA16(b0 + dOff + 4096,          pA + d64);
        CPA16(b0 + 8192  + dOff,         pW);
        CPA16(b0 + 8192  + dOff + 4096,  pW + d64);
        CPA16(b0 + 16384 + dOff,         pW + dWl);
        CPA16(b0 + 16384 + dOff + 4096,  pW + dWl + d64);
        CPCOMMIT();
    }

    for (int kb = 0; kb < nk; kb++) {
        CPWAIT0();
        __syncthreads();
        if (kb + 1 < nk) {
            int ko = (kb + 1) << 5;
            unsigned b0 = sbase + ((unsigned)((kb + 1) & 1)) * 24576u;
            CPA16(b0 + dOff,                 pA + ko);
            CPA16(b0 + dOff + 4096,          pA + d64 + ko);
            CPA16(b0 + 8192  + dOff,         pW + ko);
            CPA16(b0 + 8192  + dOff + 4096,  pW + d64 + ko);
            CPA16(b0 + 16384 + dOff,         pW + dWl + ko);
            CPA16(b0 + 16384 + dOff + 4096,  pW + dWl + d64 + ko);
            CPCOMMIT();
        }

        unsigned bA = sbase + ((unsigned)(kb & 1)) * 24576u;
        unsigned bWh = bA + 8192, bWl = bA + 16384;

        #pragma unroll
        for (int s = 0; s < 2; s++) {
            unsigned so = s << 5;
            unsigned aA[4][4], bH[2][4], bL[2][4];
            #pragma unroll
            for (int i = 0; i < 4; i++) LDSM4(aA[i], bA + SW64(aOff[i] + so));
            #pragma unroll
            for (int j = 0; j < 2; j++) LDSM4(bH[j], bWh + SW64(bOff[j] + so));
            #pragma unroll
            for (int i = 0; i < 4; i++)
                #pragma unroll
                for (int j = 0; j < 2; j++) {
                    MMA_F16(acc[i][2*j],   aA[i], bH[j][0], bH[j][2]);
                    MMA_F16(acc[i][2*j+1], aA[i], bH[j][1], bH[j][3]);
                }
            #pragma unroll
            for (int j = 0; j < 2; j++) LDSM4(bL[j], bWl + SW64(bOff[j] + so));
            #pragma unroll
            for (int i = 0; i < 4; i++)
                #pragma unroll
                for (int j = 0; j < 2; j++) {
                    MMA_F16(acc[i][2*j],   aA[i], bL[j][0], bL[j][2]);
                    MMA_F16(acc[i][2*j+1], aA[i], bL[j][1], bL[j][3]);
                }
        }
        __syncthreads();
    }

    #pragma unroll
    for (int i = 0; i < 4; i++) {
        #pragma unroll
        for (int j = 0; j < 4; j++) {
            int row0 = bm + m0 + 16 * i + fr;
            int col  = bn + n0 + 8 * j + kp * 2;
            #pragma unroll
            for (int half = 0; half < 2; half++) {
                int row = row0 + half * 8;
                float v0 = acc[i][j][2 * half + 0];
                float v1 = acc[i][j][2 * half + 1];
                size_t off = (size_t)row * N + col;
                if (MODE == 0) {
                    *(float2*)(C + off) = make_float2(v0, v1);
                } else if (MODE == 1) {
                    float2 xr = *(const float2*)(X + off);
                    *(float2*)(C + off) = make_float2(v0 + xr.x, v1 + xr.y);
                } else {
                    float2 gr = *(const float2*)(X + off);
                    v0 *= gr.x / (1.0f + expf(-gr.x));
                    v1 *= gr.y / (1.0f + expf(-gr.y));
                    *(unsigned*)(C16 + off) = pack_h2(v0 * 0.0625f, v1 * 0.0625f);
                }
            }
        }
    }
}

// ---------------- RoPE + split of Q/K (bf16 hi/lo) and V (fp16 hi/lo) ----------------
__global__ void rope_split_kernel(const int* __restrict__ pos_ids) {
    int gid = blockIdx.x * blockDim.x + threadIdx.x;
    int d = gid & 31;
    int slot = (gid >> 5) % 56;
    int tok = (gid >> 5) / 56;
    if (tok >= M_TOK) return;
    if (slot < 40) {
        float p = (float)pos_ids[tok];
        float inv = powf(10000.0f, -(float)d * (1.0f / 32.0f));
        float ang = p * inv;
        float s, c;
        sincosf(ang, &s, &c);
        const float* base;
        __nv_bfloat16 *dh, *dl;
        if (slot < NH) {
            base = g_qkv + (size_t)tok * QKV_N + (slot << 6);
            dh = g_qp_h + (size_t)tok * H + (slot << 6);
            dl = g_qp_l + (size_t)tok * H + (slot << 6);
        } else {
            base = g_qkv + (size_t)tok * QKV_N + 2048 + ((slot - NH) << 6);
            dh = g_kp_h + (size_t)tok * 512 + ((slot - NH) << 6);
            dl = g_kp_l + (size_t)tok * 512 + ((slot - NH) << 6);
        }
        float x1 = base[d];
        float x2 = base[d + 32];
        float y1 = x1 * c - x2 * s;
        float y2 = x2 * c + x1 * s;
        if (slot < NH) { y1 *= 0.125f; y2 *= 0.125f; }
        float h1, l1, h2, l2;
        split1(y1, h1, l1);
        split1(y2, h2, l2);
        dh[d]      = __float2bfloat16(h1);
        dl[d]      = __float2bfloat16(l1);
        dh[d + 32] = __float2bfloat16(h2);
        dl[d + 32] = __float2bfloat16(l2);
    } else {
        int e = ((slot - 40) << 5) + d;
        float v = g_qkv[(size_t)tok * QKV_N + 2560 + e];
        float hv, lv;
        split1h(v, hv, lv);
        g_vp_h[(size_t)tok * 512 + e] = __float2half_rn(hv);
        g_vp_l[(size_t)tok * 512 + e] = __float2half_rn(lv);
    }
}

// ---------------- Tensor-core flash attention (causal, GQA) -> fp16 plane ----------------
// Phase A: bf16 3-pass (Q/K). Phase C: fp16 2-pass (P single x V hi/lo).
__global__ void __launch_bounds__(256, 2) attn_kernel() {
    extern __shared__ unsigned char smn[];
    unsigned sb = (unsigned)__cvta_generic_to_shared(smn);
    const unsigned QhO = 0,     QlO = 8192,  KhO = 16384, KlO = 24576;
    const unsigned VhO = 32768, VlO = 40960, PO = 49152;
    float* St   = (float*)(smn + 57344);    // 64 x 68 fp32
    float* corr = (float*)(smn + 74752);    // 64
    float* linv = (float*)(smn + 75008);    // 64

    int qt = (SEQ / 64 - 1) - blockIdx.x;   // longest-first scheduling
    int h = blockIdx.y, b = blockIdx.z;
    int kh = h >> 2;
    int tid = threadIdx.x, warp = tid >> 5, lane = tid & 31;
    int m0 = (warp >> 1) << 4;
    int n0 = (warp & 1) << 5;
    int lr = lane & 15, lc = lane >> 4;
    int fr = lane >> 2, kp = lane & 3;
    int qr = tid >> 2, qc = tid & 3;

    ptrdiff_t dQl = g_qp_l - g_qp_h;
    ptrdiff_t dKl = g_kp_l - g_kp_h;
    ptrdiff_t dVl = g_vp_l - g_vp_h;

    int sr0 = tid >> 3, sc0 = tid & 7;
    unsigned sOffA = SW128X(sr0 * 128 + sc0 * 16);
    unsigned sOffB = SW128X((sr0 + 32) * 128 + sc0 * 16);

    {
        const __nv_bfloat16* qb = g_qp_h + (size_t)(b * SEQ + (qt << 6) + sr0) * H + (h << 6) + sc0 * 8;
        const __nv_bfloat16* qb2 = qb + (size_t)32 * H;
        *(uint4*)(smn + QhO + sOffA) = *(const uint4*)qb;
        *(uint4*)(smn + QlO + sOffA) = *(const uint4*)(qb + dQl);
        *(uint4*)(smn + QhO + sOffB) = *(const uint4*)qb2;
        *(uint4*)(smn + QlO + sOffB) = *(const uint4*)(qb2 + dQl);
    }

    float oacc[4][4];
    #pragma unroll
    for (int j = 0; j < 4; j++)
        #pragma unroll
        for (int r = 0; r < 4; r++) oacc[j][r] = 0.0f;
    float mrow = -INFINITY, lrow = 0.0f;

    for (int kt = 0; kt <= qt; kt++) {
        __syncthreads();
        int tokbase = b * SEQ + (kt << 6);
        {
            const __nv_bfloat16* kb  = g_kp_h + (size_t)(tokbase + sr0) * 512 + (kh << 6) + sc0 * 8;
            const __nv_bfloat16* kb2 = kb + (size_t)32 * 512;
            const __half* vb  = g_vp_h + (size_t)(tokbase + sr0) * 512 + (kh << 6) + sc0 * 8;
            const __half* vb2 = vb + (size_t)32 * 512;
            uint4 k0 = *(const uint4*)kb;
            uint4 k0l = *(const uint4*)(kb + dKl);
            uint4 k1 = *(const uint4*)kb2;
            uint4 k1l = *(const uint4*)(kb2 + dKl);
            uint4 v0 = *(const uint4*)vb;
            uint4 v0l = *(const uint4*)(vb + dVl);
            uint4 v1 = *(const uint4*)vb2;
            uint4 v1l = *(const uint4*)(vb2 + dVl);
            *(uint4*)(smn + KhO + sOffA) = k0;
            *(uint4*)(smn + KlO + sOffA) = k0l;
            *(uint4*)(smn + KhO + sOffB) = k1;
            *(uint4*)(smn + KlO + sOffB) = k1l;
            *(uint4*)(smn + VhO + sOffA) = v0;
            *(uint4*)(smn + VlO + sOffA) = v0l;
            *(uint4*)(smn + VhO + sOffB) = v1;
            *(uint4*)(smn + VlO + sOffB) = v1l;
        }
        __syncthreads();

        // phase A: S = Q K^T (bf16 3-pass)
        float accS[4][4];
        #pragma unroll
        for (int j = 0; j < 4; j++)
            #pragma unroll
            for (int r = 0; r < 4; r++) accS[j][r] = 0.0f;
        #pragma unroll
        for (int ks = 0; ks < 4; ks++) {
            unsigned co = 32*ks + 16*lc;
            unsigned aoff = SW128X((m0 + lr)*128 + co);
            unsigned ah[4], al[4];
            LDSM4(ah, sb + QhO + aoff);
            LDSM4(al, sb + QlO + aoff);
            #pragma unroll
            for (int j2 = 0; j2 < 2; j2++) {
                unsigned boff = SW128X((n0 + 16*j2 + lr)*128 + co);
                unsigned bh[4], bl[4];
                LDSM4(bh, sb + KhO + boff);
                LDSM4(bl, sb + KlO + boff);
                MMA_B16(accS[2*j2],   ah, bh[0], bh[2]);
                MMA_B16(accS[2*j2+1], ah, bh[1], bh[3]);
                MMA_B16(accS[2*j2],   ah, bl[0], bl[2]);
                MMA_B16(accS[2*j2+1], ah, bl[1], bl[3]);
                MMA_B16(accS[2*j2],   al, bh[0], bh[2]);
                MMA_B16(accS[2*j2+1], al, bh[1], bh[3]);
            }
        }
        bool diag = (kt == qt);
        #pragma unroll
        for (int j = 0; j < 4; j++) {
            int col = n0 + 8*j + 2*kp;
            #pragma unroll
            for (int hf = 0; hf < 2; hf++) {
                int row = m0 + fr + 8*hf;
                float v0 = accS[j][2*hf], v1 = accS[j][2*hf+1];
                if (diag) {
                    if (col > row)     v0 = -INFINITY;
                    if (col + 1 > row) v1 = -INFINITY;
                }
                *(float2*)&St[row*68 + col] = make_float2(v0, v1);
            }
        }
        __syncthreads();

        // phase B: online softmax, P -> fp16 single plane
        float* srow = &St[qr*68 + (qc<<4)];
        float tmax = -INFINITY;
        #pragma unroll
        for (int j = 0; j < 16; j++) tmax = fmaxf(tmax, srow[j]);
        tmax = fmaxf(tmax, __shfl_xor_sync(0xffffffffu, tmax, 1));
        tmax = fmaxf(tmax, __shfl_xor_sync(0xffffffffu, tmax, 2));
        float mnew = fmaxf(mrow, tmax);
        float cv = __expf(mrow - mnew);
        float psum = 0.0f;
        float pv[16];
        #pragma unroll
        for (int j = 0; j < 16; j++) { pv[j] = __expf(srow[j] - mnew); psum += pv[j]; }
        psum += __shfl_xor_sync(0xffffffffu, psum, 1);
        psum += __shfl_xor_sync(0xffffffffu, psum, 2);
        lrow = lrow * cv + psum;
        mrow = mnew;
        if (qc == 0) corr[qr] = cv;
        #pragma unroll
        for (int p = 0; p < 8; p++) {
            unsigned off = SW128X(qr*128 + qc*32 + p*4);
            *(unsigned*)(smn + PO + off) = pack_h2(pv[2*p], pv[2*p+1]);
        }
        __syncthreads();

        // phase C: O = O*corr + P V (fp16 2-pass: P single x V hi/lo)
        float c0v = corr[m0 + fr], c1v = corr[m0 + fr + 8];
        #pragma unroll
        for (int j = 0; j < 4; j++) {
            oacc[j][0] *= c0v; oacc[j][1] *= c0v;
            oacc[j][2] *= c1v; oacc[j][3] *= c1v;
        }
        #pragma unroll
        for (int ks = 0; ks < 4; ks++) {
            unsigned aoff = SW128X((m0 + lr)*128 + 32*ks + 16*lc);
            unsigned pf[4];
            LDSM4(pf, sb + PO + aoff);
            #pragma unroll
            for (int j2 = 0; j2 < 2; j2++) {
                unsigned boff = SW128X((16*ks + lr)*128 + (n0 + 16*j2)*2 + 16*lc);
                unsigned bh[4], bl[4];
                LDSM4T(bh, sb + VhO + boff);
                LDSM4T(bl, sb + VlO + boff);
                MMA_F16(oacc[2*j2],   pf, bh[0], bh[1]);
                MMA_F16(oacc[2*j2+1], pf, bh[2], bh[3]);
                MMA_F16(oacc[2*j2],   pf, bl[0], bl[1]);
                MMA_F16(oacc[2*j2+1], pf, bl[2], bl[3]);
            }
        }
    }

    if (qc == 0) linv[qr] = 1.0f / lrow;
    __syncthreads();
    float i0 = linv[m0 + fr], i1 = linv[m0 + fr + 8];
    #pragma unroll
    for (int j = 0; j < 4; j++) {
        int d = n0 + 8*j + 2*kp;
        #pragma unroll
        for (int hf = 0; hf < 2; hf++) {
            int row = m0 + fr + 8*hf;
            float sc = hf ? i1 : i0;
            float v0 = oacc[j][2*hf] * sc, v1 = oacc[j][2*hf+1] * sc;
            size_t idx = (((size_t)(b*SEQ + (qt<<6) + row)*NH + h) << 6) + d;
            *(unsigned*)(g_ao16 + idx) = pack_h2(v0, v1);
        }
    }
}

// ---------------- launch ----------------
extern "C" void kernel_launch(void* const* d_in, const int* in_sizes, int n_in,
                              void* d_out, int out_size) {
    (void)in_sizes; (void)n_in; (void)out_size;
    const float* hs     = (const float*)d_in[0];
    const int*   pos    = (const int*)d_in[2];
    const float* q_w    = (const float*)d_in[3];
    const float* k_w    = (const float*)d_in[4];
    const float* v_w    = (const float*)d_in[5];
    const float* o_w    = (const float*)d_in[6];
    const float* gate_w = (const float*)d_in[7];
    const float* up_w   = (const float*)d_in[8];
    const float* down_w = (const float*)d_in[9];
    const float* ln1    = (const float*)d_in[10];
    const float* ln2    = (const float*)d_in[11];
    const float* kkp    = (const float*)d_in[12];
    const float* aap    = (const float*)d_in[13];
    float* out = (float*)d_out;

    float *qkv, *hid, *gate;
    __nv_bfloat16 *xnh, *xnl, *wh, *wl;
    __half *w16h, *w16l, *xn16, *act16, *ao16;
    cudaGetSymbolAddress((void**)&qkv,   g_qkv);
    cudaGetSymbolAddress((void**)&hid,   g_hidden);
    cudaGetSymbolAddress((void**)&gate,  g_gate);
    cudaGetSymbolAddress((void**)&xnh,   g_xn_h);
    cudaGetSymbolAddress((void**)&xnl,   g_xn_l);
    cudaGetSymbolAddress((void**)&wh,    g_w_h);
    cudaGetSymbolAddress((void**)&wl,    g_w_l);
    cudaGetSymbolAddress((void**)&w16h,  g_w16_h);
    cudaGetSymbolAddress((void**)&w16l,  g_w16_l);
    cudaGetSymbolAddress((void**)&xn16,  g_xn16);
    cudaGetSymbolAddress((void**)&act16, g_act16);
    cudaGetSymbolAddress((void**)&ao16,  g_ao16);

    cudaFuncSetAttribute(attn_kernel, cudaFuncAttributeMaxDynamicSharedMemorySize, ATTN_SMEM);
    cudaFuncSetAttribute(gemm_mma,    cudaFuncAttributeMaxDynamicSharedMemorySize, GEMM_SMEM);
    cudaFuncSetAttribute(gemm_f16<0>, cudaFuncAttributeMaxDynamicSharedMemorySize, GEMM16_SMEM);
    cudaFuncSetAttribute(gemm_f16<1>, cudaFuncAttributeMaxDynamicSharedMemorySize, GEMM16_SMEM);
    cudaFuncSetAttribute(gemm_f16<2>, cudaFuncAttributeMaxDynamicSharedMemorySize, GEMM16_SMEM);

    dim3 blk(256);

    // 0) weight prepass: QKV -> bf16 split; O + MLP -> fp16 split (down pre-scaled x16)
    binsplit_kernel<<<(2048*2048)/1024, blk>>>(q_w, wh + OFF_Q, wl + OFF_Q, kkp, aap);
    binsplit_kernel<<<(512*2048)/1024,  blk>>>(k_w, wh + OFF_K, wl + OFF_K, kkp, aap);
    binsplit_kernel<<<(512*2048)/1024,  blk>>>(v_w, wh + OFF_V, wl + OFF_V, kkp, aap);
    binsplit16_kernel<<<(2048*2048)/1024, blk>>>(o_w,    w16h + OFF16_O, w16l + OFF16_O, kkp, aap, 1.0f);
    binsplit16_kernel<<<(5632*2048)/1024, blk>>>(gate_w, w16h + OFF16_G, w16l + OFF16_G, kkp, aap, 1.0f);
    binsplit16_kernel<<<(5632*2048)/1024, blk>>>(up_w,   w16h + OFF16_U, w16l + OFF16_U, kkp, aap, 1.0f);
    binsplit16_kernel<<<(2048*5632)/1024, blk>>>(down_w, w16h + OFF16_D, w16l + OFF16_D, kkp, aap, 16.0f);

    // 1) rmsnorm 1 -> bf16 planes
    rmsnorm_kernel<<<M_TOK, blk>>>(hs, ln1, xnh, xnl);
    // 2) fused QKV projection (bf16 3-pass)
    gemm_mma<<<dim3(QKV_N/128, M_TOK/128), blk, GEMM_SMEM>>>(xnh, xnl, wh+OFF_Q, wl+OFF_Q, qkv, QKV_N, H);
    // 3) rope + split -> attention planes
    rope_split_kernel<<<(M_TOK*56*32)/256, blk>>>(pos);
    // 4) attention -> fp16 plane
    attn_kernel<<<dim3(SEQ/64, NH, BATCH), blk, ATTN_SMEM>>>();
    // 5) o-proj + residual (fp16 2-pass)
    gemm_f16<1><<<dim3(H/128, M_TOK/128), blk, GEMM16_SMEM>>>(ao16, w16h+OFF16_O, w16l+OFF16_O, hs, hid, nullptr, H, H);
    // 6) rmsnorm 2 -> fp16 plane
    rmsnorm16_kernel<<<M_TOK, blk>>>(hid, ln2, xn16);
    // 7) gate proj (fp16 2-pass, fp32 out)
    gemm_f16<0><<<dim3(FF/128, M_TOK/128), blk, GEMM16_SMEM>>>(xn16, w16h+OFF16_G, w16l+OFF16_G, nullptr, gate, nullptr, FF, H);
    // 8) up proj, fused silu(gate)*up -> fp16 act (x1/16)
    gemm_f16<2><<<dim3(FF/128, M_TOK/128), blk, GEMM16_SMEM>>>(xn16, w16h+OFF16_U, w16l+OFF16_U, gate, nullptr, act16, FF, H);
    // 9) down proj (weights x16) + residual -> out
    gemm_f16<1><<<dim3(H/128, M_TOK/128), blk, GEMM16_SMEM>>>(act16, w16h+OFF16_D, w16l+OFF16_D, hid, out, nullptr, H, FF);
}

// round 16
// speedup vs baseline: 1.6886x; 1.0297x over previous
#include <cuda_runtime.h>
#include <cuda_bf16.h>
#include <cuda_fp16.h>
#include <math.h>

#define H      2048
#define NH     32
#define NKV    8
#define HD     64
#define GROUPS 4
#define FF     5632
#define BATCH  2
#define SEQ    2048
#define M_TOK  (BATCH*SEQ)
#define QKV_N  3072

#define ATTN_SMEM   108032
#define GEMM_SMEM   65536
#define GEMM16_SMEM 49152

// bf16 weight planes (QKV only)
#define OFF_Q  ((size_t)0)
#define OFF_K  (OFF_Q + (size_t)2048*2048)
#define OFF_V  (OFF_K + (size_t)512*2048)
#define W_TOTAL (OFF_V + (size_t)512*2048)
// fp16 weight planes (O + MLP)
#define OFF16_O ((size_t)0)
#define OFF16_G (OFF16_O + (size_t)2048*2048)
#define OFF16_U (OFF16_G + (size_t)5632*2048)
#define OFF16_D (OFF16_U + (size_t)5632*2048)
#define W16_TOTAL (OFF16_D + (size_t)2048*5632)

// ---------------- scratch (device globals: allocation-guard safe) ----------------
__device__ float g_qkv[M_TOK*QKV_N];
__device__ float g_hidden[M_TOK*H];
__device__ float g_gate[M_TOK*FF];
__device__ __nv_bfloat16 g_xn_h[M_TOK*H];
__device__ __nv_bfloat16 g_xn_l[M_TOK*H];
__device__ __nv_bfloat16 g_w_h[W_TOTAL];
__device__ __nv_bfloat16 g_w_l[W_TOTAL];
__device__ __half g_w16_h[W16_TOTAL];
__device__ __half g_w16_l[W16_TOTAL];
__device__ __half g_xn16[M_TOK*H];
__device__ __half g_act16[M_TOK*FF];
__device__ __half g_ao16[M_TOK*H];          // attention output, fp16 single plane
// rope'd attention input planes (Q pre-scaled by 1/8); Q/K bf16, V fp16
__device__ __nv_bfloat16 g_qp_h[M_TOK*H];
__device__ __nv_bfloat16 g_qp_l[M_TOK*H];
__device__ __nv_bfloat16 g_kp_h[M_TOK*NKV*HD];
__device__ __nv_bfloat16 g_kp_l[M_TOK*NKV*HD];
__device__ __half g_vp_h[M_TOK*NKV*HD];
__device__ __half g_vp_l[M_TOK*NKV*HD];

// ---------------- helpers ----------------
__device__ __forceinline__ unsigned pack_bf2(float a, float b) {
    __nv_bfloat162 t = __floats2bfloat162_rn(a, b);
    return *(unsigned*)&t;
}
__device__ __forceinline__ unsigned pack_h2(float a, float b) {
    __half2 t = __floats2half2_rn(a, b);
    return *(unsigned*)&t;
}
__device__ __forceinline__ void split1(float x, float& hi, float& lo) {
    __nv_bfloat16 hb = __float2bfloat16(x);
    hi = __bfloat162float(hb);
    lo = x - hi;
}
__device__ __forceinline__ void split1h(float x, float& hi, float& lo) {
    __half hb = __float2half_rn(x);
    hi = __half2float(hb);
    lo = x - hi;
}

#define SW64(x)   ((unsigned)(x) ^ ((((unsigned)(x)) >> 3) & 0x30u))
#define SW128X(x) ((unsigned)(x) ^ ((((unsigned)(x)) >> 3) & 0x70u))

#define CPA16(dst, src) \
    asm volatile("cp.async.cg.shared.global [%0], [%1], 16;" :: "r"(dst), "l"(src))
#define CPCOMMIT() asm volatile("cp.async.commit_group;")
#define CPWAIT0()  asm volatile("cp.async.wait_group 0;")

#define LDSM4(r, a) \
    asm volatile("ldmatrix.sync.aligned.m8n8.x4.shared.b16 {%0,%1,%2,%3}, [%4];" \
                 : "=r"((r)[0]), "=r"((r)[1]), "=r"((r)[2]), "=r"((r)[3]) : "r"(a))
#define LDSM4T(r, a) \
    asm volatile("ldmatrix.sync.aligned.m8n8.x4.trans.shared.b16 {%0,%1,%2,%3}, [%4];" \
                 : "=r"((r)[0]), "=r"((r)[1]), "=r"((r)[2]), "=r"((r)[3]) : "r"(a))

#define MMA_B16(c, a, b0v, b1v) \
    asm volatile("mma.sync.aligned.m16n8k16.row.col.f32.bf16.bf16.f32 " \
                 "{%0,%1,%2,%3},{%4,%5,%6,%7},{%8,%9},{%0,%1,%2,%3};" \
                 : "+f"((c)[0]), "+f"((c)[1]), "+f"((c)[2]), "+f"((c)[3]) \
                 : "r"((a)[0]), "r"((a)[1]), "r"((a)[2]), "r"((a)[3]), "r"(b0v), "r"(b1v))
#define MMA_F16(c, a, b0v, b1v) \
    asm volatile("mma.sync.aligned.m16n8k16.row.col.f32.f16.f16.f32 " \
                 "{%0,%1,%2,%3},{%4,%5,%6,%7},{%8,%9},{%0,%1,%2,%3};" \
                 : "+f"((c)[0]), "+f"((c)[1]), "+f"((c)[2]), "+f"((c)[3]) \
                 : "r"((a)[0]), "r"((a)[1]), "r"((a)[2]), "r"((a)[3]), "r"(b0v), "r"(b1v))

// ---------------- weight binarize + bf16 hi/lo split prepass ----------------
__global__ void binsplit_kernel(const float* __restrict__ src,
                                __nv_bfloat16* __restrict__ dh,
                                __nv_bfloat16* __restrict__ dl,
                                const float* __restrict__ kkp, const float* __restrict__ aap) {
    const float kk = kkp[0], aa = aap[0];
    size_t i = ((size_t)blockIdx.x * 256 + threadIdx.x) * 4;
    float4 w = *(const float4*)(src + i);
    float v[4] = {w.x, w.y, w.z, w.w};
    float hv[4], lv[4];
    #pragma unroll
    for (int j = 0; j < 4; j++) {
        float b = aa * fminf(fmaxf(kk * v[j], -1.0f), 1.0f);
        split1(b, hv[j], lv[j]);
    }
    *(uint2*)(dh + i) = make_uint2(pack_bf2(hv[0], hv[1]), pack_bf2(hv[2], hv[3]));
    *(uint2*)(dl + i) = make_uint2(pack_bf2(lv[0], lv[1]), pack_bf2(lv[2], lv[3]));
}

// ---------------- weight binarize + fp16 hi/lo split prepass (with output scale) ----------------
__global__ void binsplit16_kernel(const float* __restrict__ src,
                                  __half* __restrict__ dh,
                                  __half* __restrict__ dl,
                                  const float* __restrict__ kkp, const float* __restrict__ aap,
                                  float scale) {
    const float kk = kkp[0], aa = aap[0];
    size_t i = ((size_t)blockIdx.x * 256 + threadIdx.x) * 4;
    float4 w = *(const float4*)(src + i);
    float v[4] = {w.x, w.y, w.z, w.w};
    float hv[4], lv[4];
    #pragma unroll
    for (int j = 0; j < 4; j++) {
        float b = aa * fminf(fmaxf(kk * v[j], -1.0f), 1.0f) * scale;
        split1h(b, hv[j], lv[j]);
    }
    *(uint2*)(dh + i) = make_uint2(pack_h2(hv[0], hv[1]), pack_h2(hv[2], hv[3]));
    *(uint2*)(dl + i) = make_uint2(pack_h2(lv[0], lv[1]), pack_h2(lv[2], lv[3]));
}

// ---------------- RMSNorm -> bf16 hi/lo planes ----------------
__global__ void rmsnorm_kernel(const float* __restrict__ x, const float* __restrict__ w,
                               __nv_bfloat16* __restrict__ yh, __nv_bfloat16* __restrict__ yl) {
    int row = blockIdx.x;
    const float4* xr = (const float4*)(x + (size_t)row * H);
    const float4* wv = (const float4*)w;
    int tid = threadIdx.x;
    float4 a = xr[tid];
    float4 b = xr[tid + 256];
    float ss = a.x*a.x + a.y*a.y + a.z*a.z + a.w*a.w
             + b.x*b.x + b.y*b.y + b.z*b.z + b.w*b.w;
    #pragma unroll
    for (int o = 16; o; o >>= 1) ss += __shfl_xor_sync(0xffffffffu, ss, o);
    __shared__ float ws[8];
    if ((tid & 31) == 0) ws[tid >> 5] = ss;
    __syncthreads();
    float tot = ws[0]+ws[1]+ws[2]+ws[3]+ws[4]+ws[5]+ws[6]+ws[7];
    float r = rsqrtf(tot * (1.0f / (float)H) + 1e-5f);
    float4 w0 = wv[tid], w1 = wv[tid + 256];
    float o0[4] = {a.x*r*w0.x, a.y*r*w0.y, a.z*r*w0.z, a.w*r*w0.w};
    float o1[4] = {b.x*r*w1.x, b.y*r*w1.y, b.z*r*w1.z, b.w*r*w1.w};
    float h0[4], l0[4], h1[4], l1[4];
    #pragma unroll
    for (int j = 0; j < 4; j++) { split1(o0[j], h0[j], l0[j]); split1(o1[j], h1[j], l1[j]); }
    size_t base = (size_t)row * H + 4 * tid;
    *(uint2*)(yh + base)        = make_uint2(pack_bf2(h0[0],h0[1]), pack_bf2(h0[2],h0[3]));
    *(uint2*)(yl + base)        = make_uint2(pack_bf2(l0[0],l0[1]), pack_bf2(l0[2],l0[3]));
    *(uint2*)(yh + base + 1024) = make_uint2(pack_bf2(h1[0],h1[1]), pack_bf2(h1[2],h1[3]));
    *(uint2*)(yl + base + 1024) = make_uint2(pack_bf2(l1[0],l1[1]), pack_bf2(l1[2],l1[3]));
}

// ---------------- RMSNorm -> fp16 single plane ----------------
__global__ void rmsnorm16_kernel(const float* __restrict__ x, const float* __restrict__ w,
                                 __half* __restrict__ y) {
    int row = blockIdx.x;
    const float4* xr = (const float4*)(x + (size_t)row * H);
    const float4* wv = (const float4*)w;
    int tid = threadIdx.x;
    float4 a = xr[tid];
    float4 b = xr[tid + 256];
    float ss = a.x*a.x + a.y*a.y + a.z*a.z + a.w*a.w
             + b.x*b.x + b.y*b.y + b.z*b.z + b.w*b.w;
    #pragma unroll
    for (int o = 16; o; o >>= 1) ss += __shfl_xor_sync(0xffffffffu, ss, o);
    __shared__ float ws[8];
    if ((tid & 31) == 0) ws[tid >> 5] = ss;
    __syncthreads();
    float tot = ws[0]+ws[1]+ws[2]+ws[3]+ws[4]+ws[5]+ws[6]+ws[7];
    float r = rsqrtf(tot * (1.0f / (float)H) + 1e-5f);
    float4 w0 = wv[tid], w1 = wv[tid + 256];
    size_t base = (size_t)row * H + 4 * tid;
    *(uint2*)(y + base)        = make_uint2(pack_h2(a.x*r*w0.x, a.y*r*w0.y), pack_h2(a.z*r*w0.z, a.w*r*w0.w));
    *(uint2*)(y + base + 1024) = make_uint2(pack_h2(b.x*r*w1.x, b.y*r*w1.y), pack_h2(b.z*r*w1.z, b.w*r*w1.w));
}

// ---------------- tensor-core GEMM: bf16 3-pass (QKV projection) ----------------
__global__ void __launch_bounds__(256, 2) gemm_mma(
    const __nv_bfloat16* __restrict__ Ah, const __nv_bfloat16* __restrict__ Al,
    const __nv_bfloat16* __restrict__ Wh, const __nv_bfloat16* __restrict__ Wl,
    float* __restrict__ C, int N, int K)
{
    extern __shared__ unsigned char smem[];
    unsigned sbase = (unsigned)__cvta_generic_to_shared(smem);

    int tid = threadIdx.x;
    int bm = blockIdx.y << 7, bn = blockIdx.x << 7;

    int r0 = tid >> 2, c0 = tid & 3;
    const __nv_bfloat16* pA = Ah + (size_t)(bm + r0) * K + c0 * 8;
    const __nv_bfloat16* pW = Wh + (size_t)(bn + r0) * K + c0 * 8;
    ptrdiff_t dAl = Al - Ah;
    ptrdiff_t dWl = Wl - Wh;
    ptrdiff_t d64 = (ptrdiff_t)64 * K;
    unsigned dOff = SW64(64 * r0 + 16 * c0);

    int warp = tid >> 5, lane = tid & 31;
    int m0 = (warp & 1) << 6;
    int n0 = (warp >> 1) << 5;
    int lr = lane & 15;
    int lc = lane >> 4;
    unsigned aOff[4], bOff[2];
    #pragma unroll
    for (int i = 0; i < 4; i++) aOff[i] = 64u * (m0 + 16 * i + lr) + 16u * lc;
    #pragma unroll
    for (int j = 0; j < 2; j++) bOff[j] = 64u * (n0 + 16 * j + lr) + 16u * lc;

    int fr = lane >> 2, kp = lane & 3;

    float acc[4][4][4];
    #pragma unroll
    for (int i = 0; i < 4; i++)
        #pragma unroll
        for (int j = 0; j < 4; j++)
            #pragma unroll
            for (int r = 0; r < 4; r++) acc[i][j][r] = 0.0f;

    int nk = K >> 5;

    {
        unsigned b0 = sbase;
        CPA16(b0 + dOff,                 pA);
        CPA16(b0 + dOff + 4096,          pA + d64);
        CPA16(b0 + 8192  + dOff,         pA + dAl);
        CPA16(b0 + 8192  + dOff + 4096,  pA + dAl + d64);
        CPA16(b0 + 16384 + dOff,         pW);
        CPA16(b0 + 16384 + dOff + 4096,  pW + d64);
        CPA16(b0 + 24576 + dOff,         pW + dWl);
        CPA16(b0 + 24576 + dOff + 4096,  pW + dWl + d64);
        CPCOMMIT();
    }

    for (int kb = 0; kb < nk; kb++) {
        CPWAIT0();
        __syncthreads();
        if (kb + 1 < nk) {
            int ko = (kb + 1) << 5;
            unsigned b0 = sbase + (((kb + 1) & 1) << 15);
            CPA16(b0 + dOff,                 pA + ko);
            CPA16(b0 + dOff + 4096,          pA + d64 + ko);
            CPA16(b0 + 8192  + dOff,         pA + dAl + ko);
            CPA16(b0 + 8192  + dOff + 4096,  pA + dAl + d64 + ko);
            CPA16(b0 + 16384 + dOff,         pW + ko);
            CPA16(b0 + 16384 + dOff + 4096,  pW + d64 + ko);
            CPA16(b0 + 24576 + dOff,         pW + dWl + ko);
            CPA16(b0 + 24576 + dOff + 4096,  pW + dWl + d64 + ko);
            CPCOMMIT();
        }

        unsigned bAh = sbase + ((kb & 1) << 15);
        unsigned bAl = bAh + 8192, bWh = bAh + 16384, bWl = bAh + 24576;

        #pragma unroll
        for (int s = 0; s < 2; s++) {
            unsigned so = s << 5;
            unsigned aH[4][4], aL[4][4], bH[2][4], bL[2][4];
            #pragma unroll
            for (int i = 0; i < 4; i++) LDSM4(aH[i], bAh + SW64(aOff[i] + so));
            #pragma unroll
            for (int j = 0; j < 2; j++) LDSM4(bH[j], bWh + SW64(bOff[j] + so));
            #pragma unroll
            for (int i = 0; i < 4; i++)
                #pragma unroll
                for (int j = 0; j < 2; j++) {
                    MMA_B16(acc[i][2*j],   aH[i], bH[j][0], bH[j][2]);
                    MMA_B16(acc[i][2*j+1], aH[i], bH[j][1], bH[j][3]);
                }
            #pragma unroll
            for (int j = 0; j < 2; j++) LDSM4(bL[j], bWl + SW64(bOff[j] + so));
            #pragma unroll
            for (int i = 0; i < 4; i++)
                #pragma unroll
                for (int j = 0; j < 2; j++) {
                    MMA_B16(acc[i][2*j],   aH[i], bL[j][0], bL[j][2]);
                    MMA_B16(acc[i][2*j+1], aH[i], bL[j][1], bL[j][3]);
                }
            #pragma unroll
            for (int i = 0; i < 4; i++) LDSM4(aL[i], bAl + SW64(aOff[i] + so));
            #pragma unroll
            for (int i = 0; i < 4; i++)
                #pragma unroll
                for (int j = 0; j < 2; j++) {
                    MMA_B16(acc[i][2*j],   aL[i], bH[j][0], bH[j][2]);
                    MMA_B16(acc[i][2*j+1], aL[i], bH[j][1], bH[j][3]);
                }
        }
        // NOTE: end-of-loop __syncthreads removed (next iteration's wait+sync gives same ordering)
    }

    #pragma unroll
    for (int i = 0; i < 4; i++) {
        #pragma unroll
        for (int j = 0; j < 4; j++) {
            int row0 = bm + m0 + 16 * i + fr;
            int col  = bn + n0 + 8 * j + kp * 2;
            #pragma unroll
            for (int half = 0; half < 2; half++) {
                int row = row0 + half * 8;
                size_t off = (size_t)row * N + col;
                *(float2*)(C + off) = make_float2(acc[i][j][2*half], acc[i][j][2*half+1]);
            }
        }
    }
}

// ---------------- tensor-core GEMM: fp16 2-pass (A single plane, W hi/lo), 2 CTA/SM ----------------
// MODE 0: C fp32. MODE 1: C = acc + X (fp32). MODE 2: C16 = silu(X)*acc*(1/16) fp16.
template<int MODE>
__global__ void __launch_bounds__(256, 2) gemm_f16(
    const __half* __restrict__ A,
    const __half* __restrict__ Wh_, const __half* __restrict__ Wl_,
    const float* X, float* C, __half* C16,
    int N, int K)
{
    extern __shared__ unsigned char smem[];
    unsigned sbase = (unsigned)__cvta_generic_to_shared(smem);

    int tid = threadIdx.x;
    int bm = blockIdx.y << 7, bn = blockIdx.x << 7;

    int r0 = tid >> 2, c0 = tid & 3;
    const __half* pA = A + (size_t)(bm + r0) * K + c0 * 8;
    const __half* pW = Wh_ + (size_t)(bn + r0) * K + c0 * 8;
    ptrdiff_t dWl = Wl_ - Wh_;
    ptrdiff_t d64 = (ptrdiff_t)64 * K;
    unsigned dOff = SW64(64 * r0 + 16 * c0);

    int warp = tid >> 5, lane = tid & 31;
    int m0 = (warp & 1) << 6;
    int n0 = (warp >> 1) << 5;
    int lr = lane & 15;
    int lc = lane >> 4;
    unsigned aOff[4], bOff[2];
    #pragma unroll
    for (int i = 0; i < 4; i++) aOff[i] = 64u * (m0 + 16 * i + lr) + 16u * lc;
    #pragma unroll
    for (int j = 0; j < 2; j++) bOff[j] = 64u * (n0 + 16 * j + lr) + 16u * lc;

    int fr = lane >> 2, kp = lane & 3;

    float acc[4][4][4];
    #pragma unroll
    for (int i = 0; i < 4; i++)
        #pragma unroll
        for (int j = 0; j < 4; j++)
            #pragma unroll
            for (int r = 0; r < 4; r++) acc[i][j][r] = 0.0f;

    int nk = K >> 5;

    {
        unsigned b0 = sbase;
        CPA16(b0 + dOff,                 pA);
        CPA16(b0 + dOff + 4096,          pA + d64);
        CPA16(b0 + 8192  + dOff,         pW);
        CPA16(b0 + 8192  + dOff + 4096,  pW + d64);
        CPA16(b0 + 16384 + dOff,         pW + dWl);
        CPA16(b0 + 16384 + dOff + 4096,  pW + dWl + d64);
        CPCOMMIT();
    }

    for (int kb = 0; kb < nk; kb++) {
        CPWAIT0();
        __syncthreads();
        if (kb + 1 < nk) {
            int ko = (kb + 1) << 5;
            unsigned b0 = sbase + ((unsigned)((kb + 1) & 1)) * 24576u;
            CPA16(b0 + dOff,                 pA + ko);
            CPA16(b0 + dOff + 4096,          pA + d64 + ko);
            CPA16(b0 + 8192  + dOff,         pW + ko);
            CPA16(b0 + 8192  + dOff + 4096,  pW + d64 + ko);
            CPA16(b0 + 16384 + dOff,         pW + dWl + ko);
            CPA16(b0 + 16384 + dOff + 4096,  pW + dWl + d64 + ko);
            CPCOMMIT();
        }

        unsigned bA = sbase + ((unsigned)(kb & 1)) * 24576u;
        unsigned bWh = bA + 8192, bWl = bA + 16384;

        #pragma unroll
        for (int s = 0; s < 2; s++) {
            unsigned so = s << 5;
            unsigned aA[4][4], bH[2][4], bL[2][4];
            #pragma unroll
            for (int i = 0; i < 4; i++) LDSM4(aA[i], bA + SW64(aOff[i] + so));
            #pragma unroll
            for (int j = 0; j < 2; j++) LDSM4(bH[j], bWh + SW64(bOff[j] + so));
            #pragma unroll
            for (int i = 0; i < 4; i++)
                #pragma unroll
                for (int j = 0; j < 2; j++) {
                    MMA_F16(acc[i][2*j],   aA[i], bH[j][0], bH[j][2]);
                    MMA_F16(acc[i][2*j+1], aA[i], bH[j][1], bH[j][3]);
                }
            #pragma unroll
            for (int j = 0; j < 2; j++) LDSM4(bL[j], bWl + SW64(bOff[j] + so));
            #pragma unroll
            for (int i = 0; i < 4; i++)
                #pragma unroll
                for (int j = 0; j < 2; j++) {
                    MMA_F16(acc[i][2*j],   aA[i], bL[j][0], bL[j][2]);
                    MMA_F16(acc[i][2*j+1], aA[i], bL[j][1], bL[j][3]);
                }
        }
        // NOTE: end-of-loop __syncthreads removed
    }

    #pragma unroll
    for (int i = 0; i < 4; i++) {
        #pragma unroll
        for (int j = 0; j < 4; j++) {
            int row0 = bm + m0 + 16 * i + fr;
            int col  = bn + n0 + 8 * j + kp * 2;
            #pragma unroll
            for (int half = 0; half < 2; half++) {
                int row = row0 + half * 8;
                float v0 = acc[i][j][2 * half + 0];
                float v1 = acc[i][j][2 * half + 1];
                size_t off = (size_t)row * N + col;
                if (MODE == 0) {
                    *(float2*)(C + off) = make_float2(v0, v1);
                } else if (MODE == 1) {
                    float2 xr = *(const float2*)(X + off);
                    *(float2*)(C + off) = make_float2(v0 + xr.x, v1 + xr.y);
                } else {
                    float2 gr = *(const float2*)(X + off);
                    v0 *= gr.x / (1.0f + expf(-gr.x));
                    v1 *= gr.y / (1.0f + expf(-gr.y));
                    *(unsigned*)(C16 + off) = pack_h2(v0 * 0.0625f, v1 * 0.0625f);
                }
            }
        }
    }
}

// ---------------- RoPE + split of Q/K (bf16 hi/lo) and V (fp16 hi/lo) ----------------
__global__ void rope_split_kernel(const int* __restrict__ pos_ids) {
    int gid = blockIdx.x * blockDim.x + threadIdx.x;
    int d = gid & 31;
    int slot = (gid >> 5) % 56;
    int tok = (gid >> 5) / 56;
    if (tok >= M_TOK) return;
    if (slot < 40) {
        float p = (float)pos_ids[tok];
        float inv = powf(10000.0f, -(float)d * (1.0f / 32.0f));
        float ang = p * inv;
        float s, c;
        sincosf(ang, &s, &c);
        const float* base;
        __nv_bfloat16 *dh, *dl;
        if (slot < NH) {
            base = g_qkv + (size_t)tok * QKV_N + (slot << 6);
            dh = g_qp_h + (size_t)tok * H + (slot << 6);
            dl = g_qp_l + (size_t)tok * H + (slot << 6);
        } else {
            base = g_qkv + (size_t)tok * QKV_N + 2048 + ((slot - NH) << 6);
            dh = g_kp_h + (size_t)tok * 512 + ((slot - NH) << 6);
            dl = g_kp_l + (size_t)tok * 512 + ((slot - NH) << 6);
        }
        float x1 = base[d];
        float x2 = base[d + 32];
        float y1 = x1 * c - x2 * s;
        float y2 = x2 * c + x1 * s;
        if (slot < NH) { y1 *= 0.125f; y2 *= 0.125f; }
        float h1, l1, h2, l2;
        split1(y1, h1, l1);
        split1(y2, h2, l2);
        dh[d]      = __float2bfloat16(h1);
        dl[d]      = __float2bfloat16(l1);
        dh[d + 32] = __float2bfloat16(h2);
        dl[d + 32] = __float2bfloat16(l2);
    } else {
        int e = ((slot - 40) << 5) + d;
        float v = g_qkv[(size_t)tok * QKV_N + 2560 + e];
        float hv, lv;
        split1h(v, hv, lv);
        g_vp_h[(size_t)tok * 512 + e] = __float2half_rn(hv);
        g_vp_l[(size_t)tok * 512 + e] = __float2half_rn(lv);
    }
}

// ---------------- Tensor-core flash attention (causal, GQA) -> fp16 plane ----------------
// K/V double-buffered via cp.async (wait-after-compute); 3 syncs/iter.
__global__ void __launch_bounds__(256, 2) attn_kernel() {
    extern __shared__ unsigned char smn[];
    unsigned sb = (unsigned)__cvta_generic_to_shared(smn);
    const unsigned QhO = 0, QlO = 8192;
    // K buffers: 16384 + s*16384 (hi), +8192 (lo). V buffers: 49152 + s*16384 (hi), +8192 (lo).
    const unsigned KB0 = 16384, VB0 = 49152, PO = 81920;
    float* St   = (float*)(smn + 90112);    // 64 x 68 fp32
    float* corr = (float*)(smn + 107520);   // 64
    float* linv = (float*)(smn + 107776);   // 64

    int qt = (SEQ / 64 - 1) - blockIdx.x;   // longest-first scheduling
    int h = blockIdx.y, b = blockIdx.z;
    int kh = h >> 2;
    int tid = threadIdx.x, warp = tid >> 5, lane = tid & 31;
    int m0 = (warp >> 1) << 4;
    int n0 = (warp & 1) << 5;
    int lr = lane & 15, lc = lane >> 4;
    int fr = lane >> 2, kp = lane & 3;
    int qr = tid >> 2, qc = tid & 3;

    ptrdiff_t dQl = g_qp_l - g_qp_h;
    ptrdiff_t dKl = g_kp_l - g_kp_h;
    ptrdiff_t dVl = g_vp_l - g_vp_h;

    int sr0 = tid >> 3, sc0 = tid & 7;
    unsigned sOffA = SW128X(sr0 * 128 + sc0 * 16);
    unsigned sOffB = SW128X((sr0 + 32) * 128 + sc0 * 16);

    // Q staging (plain LDG/STS; covered by first top-of-loop sync)
    {
        const __nv_bfloat16* qb = g_qp_h + (size_t)(b * SEQ + (qt << 6) + sr0) * H + (h << 6) + sc0 * 8;
        const __nv_bfloat16* qb2 = qb + (size_t)32 * H;
        *(uint4*)(smn + QhO + sOffA) = *(const uint4*)qb;
        *(uint4*)(smn + QlO + sOffA) = *(const uint4*)(qb + dQl);
        *(uint4*)(smn + QhO + sOffB) = *(const uint4*)qb2;
        *(uint4*)(smn + QlO + sOffB) = *(const uint4*)(qb2 + dQl);
    }

    // cp.async K/V staging into buffer (kt2 & 1)
    auto stageKV = [&](int kt2) {
        int s = kt2 & 1;
        unsigned kb0 = sb + KB0 + (unsigned)s * 16384u;
        unsigned vb0 = sb + VB0 + (unsigned)s * 16384u;
        int tokbase = b * SEQ + (kt2 << 6);
        const __nv_bfloat16* kb = g_kp_h + (size_t)(tokbase + sr0) * 512 + (kh << 6) + sc0 * 8;
        const __half*        vb = g_vp_h + (size_t)(tokbase + sr0) * 512 + (kh << 6) + sc0 * 8;
        CPA16(kb0 + sOffA,        kb);
        CPA16(kb0 + 8192 + sOffA, kb + dKl);
        CPA16(kb0 + sOffB,        kb + (size_t)32 * 512);
        CPA16(kb0 + 8192 + sOffB, kb + dKl + (size_t)32 * 512);
        CPA16(vb0 + sOffA,        vb);
        CPA16(vb0 + 8192 + sOffA, vb + dVl);
        CPA16(vb0 + sOffB,        vb + (size_t)32 * 512);
        CPA16(vb0 + 8192 + sOffB, vb + dVl + (size_t)32 * 512);
        CPCOMMIT();
    };

    stageKV(0);

    float oacc[4][4];
    #pragma unroll
    for (int j = 0; j < 4; j++)
        #pragma unroll
        for (int r = 0; r < 4; r++) oacc[j][r] = 0.0f;
    float mrow = -INFINITY, lrow = 0.0f;

    for (int kt = 0; kt <= qt; kt++) {
        CPWAIT0();          // K/V tile kt landed (committed one iteration ago)
        __syncthreads();    // all warps: prev phase C done (buffers/P/St reusable), kt data visible
        if (kt + 1 <= qt) stageKV(kt + 1);   // async into other buffer, overlaps whole iteration

        unsigned bKh = sb + KB0 + (unsigned)(kt & 1) * 16384u;
        unsigned bKl = bKh + 8192;
        unsigned bVh = sb + VB0 + (unsigned)(kt & 1) * 16384u;
        unsigned bVl = bVh + 8192;

        // phase A: S = Q K^T (bf16 3-pass)
        float accS[4][4];
        #pragma unroll
        for (int j = 0; j < 4; j++)
            #pragma unroll
            for (int r = 0; r < 4; r++) accS[j][r] = 0.0f;
        #pragma unroll
        for (int ks = 0; ks < 4; ks++) {
            unsigned co = 32*ks + 16*lc;
            unsigned aoff = SW128X((m0 + lr)*128 + co);
            unsigned ah[4], al[4];
            LDSM4(ah, sb + QhO + aoff);
            LDSM4(al, sb + QlO + aoff);
            #pragma unroll
            for (int j2 = 0; j2 < 2; j2++) {
                unsigned boff = SW128X((n0 + 16*j2 + lr)*128 + co);
                unsigned bh[4], bl[4];
                LDSM4(bh, bKh + boff);
                LDSM4(bl, bKl + boff);
                MMA_B16(accS[2*j2],   ah, bh[0], bh[2]);
                MMA_B16(accS[2*j2+1], ah, bh[1], bh[3]);
                MMA_B16(accS[2*j2],   ah, bl[0], bl[2]);
                MMA_B16(accS[2*j2+1], ah, bl[1], bl[3]);
                MMA_B16(accS[2*j2],   al, bh[0], bh[2]);
                MMA_B16(accS[2*j2+1], al, bh[1], bh[3]);
            }
        }
        bool diag = (kt == qt);
        #pragma unroll
        for (int j = 0; j < 4; j++) {
            int col = n0 + 8*j + 2*kp;
            #pragma unroll
            for (int hf = 0; hf < 2; hf++) {
                int row = m0 + fr + 8*hf;
                float v0 = accS[j][2*hf], v1 = accS[j][2*hf+1];
                if (diag) {
                    if (col > row)     v0 = -INFINITY;
                    if (col + 1 > row) v1 = -INFINITY;
                }
                *(float2*)&St[row*68 + col] = make_float2(v0, v1);
            }
        }
        __syncthreads();

        // phase B: online softmax, P -> fp16 single plane
        float* srow = &St[qr*68 + (qc<<4)];
        float tmax = -INFINITY;
        #pragma unroll
        for (int j = 0; j < 16; j++) tmax = fmaxf(tmax, srow[j]);
        tmax = fmaxf(tmax, __shfl_xor_sync(0xffffffffu, tmax, 1));
        tmax = fmaxf(tmax, __shfl_xor_sync(0xffffffffu, tmax, 2));
        float mnew = fmaxf(mrow, tmax);
        float cv = __expf(mrow - mnew);
        float psum = 0.0f;
        float pv[16];
        #pragma unroll
        for (int j = 0; j < 16; j++) { pv[j] = __expf(srow[j] - mnew); psum += pv[j]; }
        psum += __shfl_xor_sync(0xffffffffu, psum, 1);
        psum += __shfl_xor_sync(0xffffffffu, psum, 2);
        lrow = lrow * cv + psum;
        mrow = mnew;
        if (qc == 0) corr[qr] = cv;
        #pragma unroll
        for (int p = 0; p < 8; p++) {
            unsigned off = SW128X(qr*128 + qc*32 + p*4);
            *(unsigned*)(smn + PO + off) = pack_h2(pv[2*p], pv[2*p+1]);
        }
        __syncthreads();

        // phase C: O = O*corr + P V (fp16 2-pass)
        float c0v = corr[m0 + fr], c1v = corr[m0 + fr + 8];
        #pragma unroll
        for (int j = 0; j < 4; j++) {
            oacc[j][0] *= c0v; oacc[j][1] *= c0v;
            oacc[j][2] *= c1v; oacc[j][3] *= c1v;
        }
        #pragma unroll
        for (int ks = 0; ks < 4; ks++) {
            unsigned aoff = SW128X((m0 + lr)*128 + 32*ks + 16*lc);
            unsigned pf[4];
            LDSM4(pf, sb + PO + aoff);
            #pragma unroll
            for (int j2 = 0; j2 < 2; j2++) {
                unsigned boff = SW128X((16*ks + lr)*128 + (n0 + 16*j2)*2 + 16*lc);
                unsigned bh[4], bl[4];
                LDSM4T(bh, bVh + boff);
                LDSM4T(bl, bVl + boff);
                MMA_F16(oacc[2*j2],   pf, bh[0], bh[1]);
                MMA_F16(oacc[2*j2+1], pf, bh[2], bh[3]);
                MMA_F16(oacc[2*j2],   pf, bl[0], bl[1]);
                MMA_F16(oacc[2*j2+1], pf, bl[2], bl[3]);
            }
        }
    }

    if (qc == 0) linv[qr] = 1.0f / lrow;
    __syncthreads();
    float i0 = linv[m0 + fr], i1 = linv[m0 + fr + 8];
    #pragma unroll
    for (int j = 0; j < 4; j++) {
        int d = n0 + 8*j + 2*kp;
        #pragma unroll
        for (int hf = 0; hf < 2; hf++) {
            int row = m0 + fr + 8*hf;
            float sc = hf ? i1 : i0;
            float v0 = oacc[j][2*hf] * sc, v1 = oacc[j][2*hf+1] * sc;
            size_t idx = (((size_t)(b*SEQ + (qt<<6) + row)*NH + h) << 6) + d;
            *(unsigned*)(g_ao16 + idx) = pack_h2(v0, v1);
        }
    }
}

// ---------------- launch ----------------
extern "C" void kernel_launch(void* const* d_in, const int* in_sizes, int n_in,
                              void* d_out, int out_size) {
    (void)in_sizes; (void)n_in; (void)out_size;
    const float* hs     = (const float*)d_in[0];
    const int*   pos    = (const int*)d_in[2];
    const float* q_w    = (const float*)d_in[3];
    const float* k_w    = (const float*)d_in[4];
    const float* v_w    = (const float*)d_in[5];
    const float* o_w    = (const float*)d_in[6];
    const float* gate_w = (const float*)d_in[7];
    const float* up_w   = (const float*)d_in[8];
    const float* down_w = (const float*)d_in[9];
    const float* ln1    = (const float*)d_in[10];
    const float* ln2    = (const float*)d_in[11];
    const float* kkp    = (const float*)d_in[12];
    const float* aap    = (const float*)d_in[13];
    float* out = (float*)d_out;

    float *qkv, *hid, *gate;
    __nv_bfloat16 *xnh, *xnl, *wh, *wl;
    __half *w16h, *w16l, *xn16, *act16, *ao16;
    cudaGetSymbolAddress((void**)&qkv,   g_qkv);
    cudaGetSymbolAddress((void**)&hid,   g_hidden);
    cudaGetSymbolAddress((void**)&gate,  g_gate);
    cudaGetSymbolAddress((void**)&xnh,   g_xn_h);
    cudaGetSymbolAddress((void**)&xnl,   g_xn_l);
    cudaGetSymbolAddress((void**)&wh,    g_w_h);
    cudaGetSymbolAddress((void**)&wl,    g_w_l);
    cudaGetSymbolAddress((void**)&w16h,  g_w16_h);
    cudaGetSymbolAddress((void**)&w16l,  g_w16_l);
    cudaGetSymbolAddress((void**)&xn16,  g_xn16);
    cudaGetSymbolAddress((void**)&act16, g_act16);
    cudaGetSymbolAddress((void**)&ao16,  g_ao16);

    cudaFuncSetAttribute(attn_kernel, cudaFuncAttributeMaxDynamicSharedMemorySize, ATTN_SMEM);
    cudaFuncSetAttribute(gemm_mma,    cudaFuncAttributeMaxDynamicSharedMemorySize, GEMM_SMEM);
    cudaFuncSetAttribute(gemm_f16<0>, cudaFuncAttributeMaxDynamicSharedMemorySize, GEMM16_SMEM);
    cudaFuncSetAttribute(gemm_f16<1>, cudaFuncAttributeMaxDynamicSharedMemorySize, GEMM16_SMEM);
    cudaFuncSetAttribute(gemm_f16<2>, cudaFuncAttributeMaxDynamicSharedMemorySize, GEMM16_SMEM);

    dim3 blk(256);

    // 0) weight prepass: QKV -> bf16 split; O + MLP -> fp16 split (down pre-scaled x16)
    binsplit_kernel<<<(2048*2048)/1024, blk>>>(q_w, wh + OFF_Q, wl + OFF_Q, kkp, aap);
    binsplit_kernel<<<(512*2048)/1024,  blk>>>(k_w, wh + OFF_K, wl + OFF_K, kkp, aap);
    binsplit_kernel<<<(512*2048)/1024,  blk>>>(v_w, wh + OFF_V, wl + OFF_V, kkp, aap);
    binsplit16_kernel<<<(2048*2048)/1024, blk>>>(o_w,    w16h + OFF16_O, w16l + OFF16_O, kkp, aap, 1.0f);
    binsplit16_kernel<<<(5632*2048)/1024, blk>>>(gate_w, w16h + OFF16_G, w16l + OFF16_G, kkp, aap, 1.0f);
    binsplit16_kernel<<<(5632*2048)/1024, blk>>>(up_w,   w16h + OFF16_U, w16l + OFF16_U, kkp, aap, 1.0f);
    binsplit16_kernel<<<(2048*5632)/1024, blk>>>(down_w, w16h + OFF16_D, w16l + OFF16_D, kkp, aap, 16.0f);

    // 1) rmsnorm 1 -> bf16 planes
    rmsnorm_kernel<<<M_TOK, blk>>>(hs, ln1, xnh, xnl);
    // 2) fused QKV projection (bf16 3-pass)
    gemm_mma<<<dim3(QKV_N/128, M_TOK/128), blk, GEMM_SMEM>>>(xnh, xnl, wh+OFF_Q, wl+OFF_Q, qkv, QKV_N, H);
    // 3) rope + split -> attention planes
    rope_split_kernel<<<(M_TOK*56*32)/256, blk>>>(pos);
    // 4) attention -> fp16 plane
    attn_kernel<<<dim3(SEQ/64, NH, BATCH), blk, ATTN_SMEM>>>();
    // 5) o-proj + residual (fp16 2-pass)
    gemm_f16<1><<<dim3(H/128, M_TOK/128), blk, GEMM16_SMEM>>>(ao16, w16h+OFF16_O, w16l+OFF16_O, hs, hid, nullptr, H, H);
    // 6) rmsnorm 2 -> fp16 plane
    rmsnorm16_kernel<<<M_TOK, blk>>>(hid, ln2, xn16);
    // 7) gate proj (fp16 2-pass, fp32 out)
    gemm_f16<0><<<dim3(FF/128, M_TOK/128), blk, GEMM16_SMEM>>>(xn16, w16h+OFF16_G, w16l+OFF16_G, nullptr, gate, nullptr, FF, H);
    // 8) up proj, fused silu(gate)*up -> fp16 act (x1/16)
    gemm_f16<2><<<dim3(FF/128, M_TOK/128), blk, GEMM16_SMEM>>>(xn16, w16h+OFF16_U, w16l+OFF16_U, gate, nullptr, act16, FF, H);
    // 9) down proj (weights x16) + residual -> out
    gemm_f16<1><<<dim3(H/128, M_TOK/128), blk, GEMM16_SMEM>>>(act16, w16h+OFF16_D, w16l+OFF16_D, hid, out, nullptr, H, FF);
}